// round 10
// baseline (speedup 1.0000x reference)
#include <cuda_runtime.h>
#include <math.h>
#include <stdint.h>

#define NTOK   4096
#define BATCH  2
#define DIM64  64
#define INNERD 256
#define ROWS   (BATCH * NTOK)   // 8192

// -------------------- device scratch --------------------
__device__ float g_xn  [ROWS * DIM64];
__device__ float g_x   [ROWS * DIM64];
__device__ float g_qkv [ROWS * INNERD * 3];
__device__ float g_dots[(size_t)NTOK * NTOK];     // reused as split-K partials after softmax
__device__ float g_attn[(size_t)NTOK * NTOK];
__device__ float g_av  [ROWS * INNERD];           // [token][z*256+dh] = [4096][512]
__device__ float g_vT  [BATCH * INNERD * NTOK];   // [512][4096]
__device__ float g_wT  [768 * 64];

// -------------------- helpers --------------------
__device__ __forceinline__ void mma_tf32(float c[4], const uint32_t a[4],
                                         uint32_t b0, uint32_t b1) {
    asm volatile(
        "mma.sync.aligned.m16n8k8.row.col.f32.tf32.tf32.f32 "
        "{%0,%1,%2,%3}, {%4,%5,%6,%7}, {%8,%9}, {%0,%1,%2,%3};"
        : "+f"(c[0]), "+f"(c[1]), "+f"(c[2]), "+f"(c[3])
        : "r"(a[0]), "r"(a[1]), "r"(a[2]), "r"(a[3]), "r"(b0), "r"(b1));
}

__device__ __forceinline__ void cp16(uint32_t dst, const void* src) {
    asm volatile("cp.async.cg.shared.global [%0], [%1], 16;" :: "r"(dst), "l"(src));
}

__device__ __forceinline__ void ldsm4(uint32_t* r, uint32_t addr) {
    asm volatile("ldmatrix.sync.aligned.m8n8.x4.shared.b16 {%0,%1,%2,%3}, [%4];"
                 : "=r"(r[0]), "=r"(r[1]), "=r"(r[2]), "=r"(r[3]) : "r"(addr));
}

// ==================== TF32 tensor-core NT GEMM, ldmatrix fragments, 2 CTAs/SM ============
// C[z][M,N] = alpha * A[z](M,K) * B[z](N,K)^T ; M,N mult of 128, K mult of 32.
// z strides are ELEMENT offsets (doubles as K-offset for split-K).
// 256 threads, 8 warps (4M x 2N), warp tile 32x64, BK=32, 2-stage cp.async.
#define SPITCH 36
#define ASTG   (128 * SPITCH)
#define GEMM_TC_SMEM (4 * ASTG * (int)sizeof(float))   // 73728 bytes

__global__ void __launch_bounds__(256, 2)
gemm_tc_k(const float* __restrict__ A, int lda, size_t sAz,
          const float* __restrict__ B, int ldb, size_t sBz,
          float* __restrict__ C, int ldc, size_t sCz,
          int K, float alpha)
{
    extern __shared__ float sm[];
    const uint32_t smb = (uint32_t)__cvta_generic_to_shared(sm);
    const int tid  = threadIdx.x;
    const int wid  = tid >> 5, lane = tid & 31;
    const int wm   = wid & 3,  wn   = wid >> 2;
    const int gid  = lane >> 2, tig = lane & 3;
    const int m0   = blockIdx.y * 128, n0 = blockIdx.x * 128;

    A += (size_t)blockIdx.z * sAz;
    B += (size_t)blockIdx.z * sBz;
    C += (size_t)blockIdx.z * sCz;

    int lrow[4], lkq[4];
    #pragma unroll
    for (int i = 0; i < 4; i++) {
        int c = tid + i * 256;
        lrow[i] = c >> 3;
        lkq[i]  = (c & 7) << 2;
    }

#define ISSUE(s, kt)                                                                   \
    {                                                                                  \
        const int _k0 = (kt) << 5;                                                     \
        _Pragma("unroll")                                                              \
        for (int i = 0; i < 4; i++) {                                                  \
            cp16(smb + (uint32_t)((((s) * ASTG) + lrow[i] * SPITCH + lkq[i]) * 4),     \
                 A + (size_t)(m0 + lrow[i]) * lda + _k0 + lkq[i]);                     \
            cp16(smb + (uint32_t)((((2 + (s)) * ASTG) + lrow[i] * SPITCH + lkq[i]) * 4), \
                 B + (size_t)(n0 + lrow[i]) * ldb + _k0 + lkq[i]);                     \
        }                                                                              \
        asm volatile("cp.async.commit_group;");                                       \
    }

    // ldmatrix per-thread fragment byte offsets
    // A (.x4): m0/m1 = rows r..r+15 col kb ; m2/m3 = same rows col kb+4
    const int arow_f = (lane & 7) + ((lane >> 3) & 1) * 8;
    const int acol_f = (lane >> 4) * 4;
    uint32_t aoff[2];
    #pragma unroll
    for (int mt = 0; mt < 2; mt++)
        aoff[mt] = (uint32_t)(((wm * 32 + mt * 16 + arow_f) * SPITCH + acol_f) * 4);
    // B (.x4, two n8-tiles per op): m0/m1 = rows nr..nr+7 cols kb,kb+4 ; m2/m3 = rows nr+8..
    const int brow_f = (lane & 7) + (lane >> 4) * 8;
    const int bcol_f = ((lane >> 3) & 1) * 4;
    uint32_t boff[4];
    #pragma unroll
    for (int j = 0; j < 4; j++)
        boff[j] = (uint32_t)(((wn * 64 + j * 16 + brow_f) * SPITCH + bcol_f) * 4);

    float acc[2][8][4];
    #pragma unroll
    for (int mt = 0; mt < 2; mt++)
        #pragma unroll
        for (int nt = 0; nt < 8; nt++)
            #pragma unroll
            for (int q = 0; q < 4; q++) acc[mt][nt][q] = 0.0f;

    const int KT = K >> 5;
    ISSUE(0, 0);

    for (int kt = 0; kt < KT; kt++) {
        const int p = kt & 1;
        if (kt + 1 < KT) {
            ISSUE(p ^ 1, kt + 1);
            asm volatile("cp.async.wait_group 1;");
        } else {
            asm volatile("cp.async.wait_group 0;");
        }
        __syncthreads();

        const uint32_t pa = smb + (uint32_t)(p * ASTG * 4);
        const uint32_t pb = smb + (uint32_t)((2 + p) * ASTG * 4);
        #pragma unroll
        for (int ks = 0; ks < 4; ks++) {
            const uint32_t kb4 = (uint32_t)(ks * 32);   // 8 floats = 32 bytes
            uint32_t fa[2][4], fb[4][4];
            ldsm4(fa[0], pa + aoff[0] + kb4);
            ldsm4(fa[1], pa + aoff[1] + kb4);
            #pragma unroll
            for (int j = 0; j < 4; j++) ldsm4(fb[j], pb + boff[j] + kb4);
            #pragma unroll
            for (int j = 0; j < 4; j++) {
                mma_tf32(acc[0][2 * j],     fa[0], fb[j][0], fb[j][1]);
                mma_tf32(acc[1][2 * j],     fa[1], fb[j][0], fb[j][1]);
                mma_tf32(acc[0][2 * j + 1], fa[0], fb[j][2], fb[j][3]);
                mma_tf32(acc[1][2 * j + 1], fa[1], fb[j][2], fb[j][3]);
            }
        }
        __syncthreads();
    }

    // epilogue
    #pragma unroll
    for (int mt = 0; mt < 2; mt++) {
        const int row = m0 + wm * 32 + mt * 16 + gid;
        #pragma unroll
        for (int nt = 0; nt < 8; nt++) {
            const int col = n0 + wn * 64 + nt * 8 + tig * 2;
            float2 v0 = make_float2(acc[mt][nt][0] * alpha, acc[mt][nt][1] * alpha);
            float2 v1 = make_float2(acc[mt][nt][2] * alpha, acc[mt][nt][3] * alpha);
            *(float2*)(C + (size_t)row * ldc + col)       = v0;
            *(float2*)(C + (size_t)(row + 8) * ldc + col) = v1;
        }
    }
#undef ISSUE
}

// -------------------- split-K reduction: o = a + b (float4) --------------------
__global__ void add2_k(const float* __restrict__ a, const float* __restrict__ b,
                       float* __restrict__ o, int n4)
{
    int i = blockIdx.x * blockDim.x + threadIdx.x;
    if (i < n4) {
        float4 x = ((const float4*)a)[i], y = ((const float4*)b)[i];
        ((float4*)o)[i] = make_float4(x.x + y.x, x.y + y.y, x.z + y.z, x.w + y.w);
    }
}

// -------------------- 32x32 transpose --------------------
__global__ void transpose_k(const float* __restrict__ src, int lds,
                            float* __restrict__ dst, int ldd)
{
    __shared__ float t[32][33];
    int c0 = blockIdx.x * 32, r0 = blockIdx.y * 32;
    int tx = threadIdx.x, ty = threadIdx.y;
    #pragma unroll
    for (int j = 0; j < 32; j += 8)
        t[ty + j][tx] = src[(size_t)(r0 + ty + j) * lds + c0 + tx];
    __syncthreads();
    #pragma unroll
    for (int j = 0; j < 32; j += 8)
        dst[(size_t)(c0 + ty + j) * ldd + r0 + tx] = t[tx][ty + j];
}

// -------------------- LayerNorm (dim 64) --------------------
__global__ void ln_k(const float* __restrict__ x, const float* __restrict__ g,
                     const float* __restrict__ b, float* __restrict__ y, int rows)
{
    int w    = blockIdx.x * 8 + (threadIdx.x >> 5);
    int lane = threadIdx.x & 31;
    if (w >= rows) return;
    const float* xr = x + (size_t)w * 64;
    float v0 = xr[lane], v1 = xr[lane + 32];
    float s = v0 + v1;
    #pragma unroll
    for (int o = 16; o > 0; o >>= 1) s += __shfl_xor_sync(0xffffffffu, s, o);
    float m  = s * (1.0f / 64.0f);
    float d0 = v0 - m, d1 = v1 - m;
    float q  = d0 * d0 + d1 * d1;
    #pragma unroll
    for (int o = 16; o > 0; o >>= 1) q += __shfl_xor_sync(0xffffffffu, q, o);
    float inv = rsqrtf(q * (1.0f / 64.0f) + 1e-5f);
    float* yr = y + (size_t)w * 64;
    yr[lane]      = d0 * inv * g[lane]      + b[lane];
    yr[lane + 32] = d1 * inv * g[lane + 32] + b[lane + 32];
}

// -------------------- small fp32 GEMM (N=64 projections, fused epilogue, z-batched) -----
__global__ void __launch_bounds__(256)
gemm_k(const float* __restrict__ A, int lda, size_t sAz,
       const float* __restrict__ B, int ldb,
       float* __restrict__ C, int ldc, size_t sCz,
       int K,
       const float* __restrict__ bias,
       const float* __restrict__ resid, int ldr, size_t sRz,
       int do_gelu)
{
    __shared__ float As[16][68];
    __shared__ float Bs[16][68];
    int tx = threadIdx.x, ty = threadIdx.y;
    int t  = ty * 16 + tx;
    int m0 = blockIdx.y * 64, n0 = blockIdx.x * 64;

    A += (size_t)blockIdx.z * sAz;
    C += (size_t)blockIdx.z * sCz;
    if (resid) resid += (size_t)blockIdx.z * sRz;

    float acc[4][4] = {};
    int ar  = t / 4;
    int ac4 = (t % 4) * 4;
    int br  = t / 16;
    int bc4 = (t % 16) * 4;

    for (int k0 = 0; k0 < K; k0 += 16) {
        const float* Ap = A + (size_t)(m0 + ar) * lda + k0 + ac4;
        #pragma unroll
        for (int q = 0; q < 4; q++) As[ac4 + q][ar] = Ap[q];
        const float* Bp = B + (size_t)(k0 + br) * ldb + n0 + bc4;
        #pragma unroll
        for (int q = 0; q < 4; q++) Bs[br][bc4 + q] = Bp[q];
        __syncthreads();
        #pragma unroll
        for (int kk = 0; kk < 16; kk++) {
            float a[4], b[4];
            #pragma unroll
            for (int i = 0; i < 4; i++) a[i] = As[kk][ty * 4 + i];
            #pragma unroll
            for (int j = 0; j < 4; j++) b[j] = Bs[kk][tx * 4 + j];
            #pragma unroll
            for (int i = 0; i < 4; i++)
                #pragma unroll
                for (int j = 0; j < 4; j++)
                    acc[i][j] = fmaf(a[i], b[j], acc[i][j]);
        }
        __syncthreads();
    }

    #pragma unroll
    for (int i = 0; i < 4; i++) {
        int row = m0 + ty * 4 + i;
        #pragma unroll
        for (int j = 0; j < 4; j++) {
            int col = n0 + tx * 4 + j;
            float v = acc[i][j];
            if (bias)    v += bias[col];
            if (do_gelu) v = 0.5f * v * (1.0f + erff(v * 0.70710678118654752f));
            if (resid)   v += resid[(size_t)row * ldr + col];
            C[(size_t)row * ldc + col] = v;
        }
    }
}

// -------------------- block reductions --------------------
__device__ __forceinline__ float blk_max(float v, float* wred, int wid, int lane) {
    #pragma unroll
    for (int o = 16; o > 0; o >>= 1) v = fmaxf(v, __shfl_xor_sync(0xffffffffu, v, o));
    if (lane == 0) wred[wid] = v;
    __syncthreads();
    float r = wred[0];
    #pragma unroll
    for (int i = 1; i < 8; i++) r = fmaxf(r, wred[i]);
    __syncthreads();
    return r;
}
__device__ __forceinline__ float blk_sum(float v, float* wred, int wid, int lane) {
    #pragma unroll
    for (int o = 16; o > 0; o >>= 1) v += __shfl_xor_sync(0xffffffffu, v, o);
    if (lane == 0) wred[wid] = v;
    __syncthreads();
    float r = 0.0f;
    #pragma unroll
    for (int i = 0; i < 8; i++) r += wred[i];
    __syncthreads();
    return r;
}

// -------------------- masked softmax, register-resident --------------------
__global__ void attn_softmax_k(const float* __restrict__ dots, const float* __restrict__ Am,
                               float* __restrict__ attn)
{
    __shared__ float wred[8];
    const int row = blockIdx.x, tid = threadIdx.x;
    const int wid = tid >> 5, lane = tid & 31;
    const float4* dr = (const float4*)(dots + (size_t)row * NTOK);
    const float4* ar = (const float4*)(Am   + (size_t)row * NTOK);
    const int dj = row >> 2, dl = row & 3;

    float4 r[4];
    float mx = -3.4e38f;
    #pragma unroll
    for (int i = 0; i < 4; i++) {
        int j = tid + i * 256;
        float4 d = dr[j], a = ar[j], v;
        v.x = (a.x > 0.0f) ? d.x : -9e15f;
        v.y = (a.y > 0.0f) ? d.y : -9e15f;
        v.z = (a.z > 0.0f) ? d.z : -9e15f;
        v.w = (a.w > 0.0f) ? d.w : -9e15f;
        if (j == dj) ((float*)&v)[dl] = 1.0f;
        r[i] = v;
        mx = fmaxf(fmaxf(fmaxf(mx, v.x), v.y), fmaxf(v.z, v.w));
    }
    mx = blk_max(mx, wred, wid, lane);

    float sum = 0.0f;
    #pragma unroll
    for (int i = 0; i < 4; i++) {
        r[i].x = __expf(r[i].x - mx); r[i].y = __expf(r[i].y - mx);
        r[i].z = __expf(r[i].z - mx); r[i].w = __expf(r[i].w - mx);
        sum += (r[i].x + r[i].y) + (r[i].z + r[i].w);
    }
    sum = blk_sum(sum, wred, wid, lane);
    float inv = 1.0f / sum;

    float4* o1 = (float4*)(attn + (size_t)row * NTOK);
    #pragma unroll
    for (int i = 0; i < 4; i++) {
        int j = tid + i * 256;
        o1[j] = make_float4(r[i].x * inv, r[i].y * inv, r[i].z * inv, r[i].w * inv);
    }
}

// ----- last layer: masked softmax (attn + attn_out) AND plain softmax (ds_out) -----
__global__ void dual_softmax_k(const float* __restrict__ dots, const float* __restrict__ Am,
                               float* __restrict__ attn, float* __restrict__ attn_out,
                               float* __restrict__ ds_out)
{
    __shared__ float wred[8];
    const int row = blockIdx.x, tid = threadIdx.x;
    const int wid = tid >> 5, lane = tid & 31;
    const float4* dr = (const float4*)(dots + (size_t)row * NTOK);
    const float4* ar = (const float4*)(Am   + (size_t)row * NTOK);
    const int dj = row >> 2, dl = row & 3;

    float4 rv[4], mv[4];
    float mxr = -3.4e38f, mxm = -3.4e38f;
    #pragma unroll
    for (int i = 0; i < 4; i++) {
        int j = tid + i * 256;
        float4 d = dr[j], a = ar[j], v;
        v.x = (a.x > 0.0f) ? d.x : -9e15f;
        v.y = (a.y > 0.0f) ? d.y : -9e15f;
        v.z = (a.z > 0.0f) ? d.z : -9e15f;
        v.w = (a.w > 0.0f) ? d.w : -9e15f;
        if (j == dj) ((float*)&v)[dl] = 1.0f;
        rv[i] = d; mv[i] = v;
        mxr = fmaxf(fmaxf(fmaxf(mxr, d.x), d.y), fmaxf(d.z, d.w));
        mxm = fmaxf(fmaxf(fmaxf(mxm, v.x), v.y), fmaxf(v.z, v.w));
    }
    mxm = blk_max(mxm, wred, wid, lane);
    mxr = blk_max(mxr, wred, wid, lane);

    float sm = 0.0f, sr = 0.0f;
    #pragma unroll
    for (int i = 0; i < 4; i++) {
        mv[i].x = __expf(mv[i].x - mxm); mv[i].y = __expf(mv[i].y - mxm);
        mv[i].z = __expf(mv[i].z - mxm); mv[i].w = __expf(mv[i].w - mxm);
        rv[i].x = __expf(rv[i].x - mxr); rv[i].y = __expf(rv[i].y - mxr);
        rv[i].z = __expf(rv[i].z - mxr); rv[i].w = __expf(rv[i].w - mxr);
        sm += (mv[i].x + mv[i].y) + (mv[i].z + mv[i].w);
        sr += (rv[i].x + rv[i].y) + (rv[i].z + rv[i].w);
    }
    sm = blk_sum(sm, wred, wid, lane);
    sr = blk_sum(sr, wred, wid, lane);
    float invm = 1.0f / sm, invr = 1.0f / sr;

    float4* o1 = (float4*)(attn     + (size_t)row * NTOK);
    float4* o2 = (float4*)(attn_out + (size_t)row * NTOK);
    float4* o3 = (float4*)(ds_out   + (size_t)row * NTOK);
    #pragma unroll
    for (int i = 0; i < 4; i++) {
        int j = tid + i * 256;
        float4 vo = make_float4(mv[i].x * invm, mv[i].y * invm, mv[i].z * invm, mv[i].w * invm);
        o1[j] = vo; o2[j] = vo;
        o3[j] = make_float4(rv[i].x * invr, rv[i].y * invr, rv[i].z * invr, rv[i].w * invr);
    }
}

// -------------------- host orchestration --------------------
extern "C" void kernel_launch(void* const* d_in, const int* in_sizes, int n_in,
                              void* d_out, int out_size)
{
    const float* embed = (const float*)d_in[0];
    const float* Am    = (const float*)d_in[1];
    const float* g1    = (const float*)d_in[2];
    const float* b1    = (const float*)d_in[3];
    const float* Wqkv  = (const float*)d_in[4];
    const float* Wout  = (const float*)d_in[5];
    const float* bout  = (const float*)d_in[6];
    const float* g2    = (const float*)d_in[7];
    const float* b2    = (const float*)d_in[8];
    const float* W1    = (const float*)d_in[9];
    const float* bb1   = (const float*)d_in[10];
    const float* W2    = (const float*)d_in[11];
    const float* bb2   = (const float*)d_in[12];
    const float* gf    = (const float*)d_in[13];
    const float* bf    = (const float*)d_in[14];

    float *xg, *xng, *qkvg, *dotsg, *attng, *avg, *vTg, *wTg;
    cudaGetSymbolAddress((void**)&xg,    g_x);
    cudaGetSymbolAddress((void**)&xng,   g_xn);
    cudaGetSymbolAddress((void**)&qkvg,  g_qkv);
    cudaGetSymbolAddress((void**)&dotsg, g_dots);
    cudaGetSymbolAddress((void**)&attng, g_attn);
    cudaGetSymbolAddress((void**)&avg,   g_av);
    cudaGetSymbolAddress((void**)&vTg,   g_vT);
    cudaGetSymbolAddress((void**)&wTg,   g_wT);

    cudaFuncSetAttribute(gemm_tc_k, cudaFuncAttributeMaxDynamicSharedMemorySize, GEMM_TC_SMEM);

    float* out_x    = (float*)d_out;
    float* out_attn = out_x + (size_t)ROWS * DIM64;
    float* out_ds   = out_attn + (size_t)NTOK * NTOK;

    dim3 blk(16, 16);
    dim3 tblk(32, 8);
    const size_t avHalf = (size_t)NTOK * 512;   // split-K partial stride (in g_dots)

    for (int l = 0; l < 2; l++) {
        const float* src = l ? xg : embed;
        // xn = LN(x)
        ln_k<<<ROWS / 8, 256>>>(src, g1 + l * 64, b1 + l * 64, xng, ROWS);
        // wT = Wqkv[l]^T
        transpose_k<<<dim3(768 / 32, 64 / 32), tblk>>>(Wqkv + (size_t)l * 64 * 768, 768, wTg, 64);
        // qkv = xn @ Wqkv[l] (NT): [8192,64] x [768,64]^T
        gemm_tc_k<<<dim3(768 / 128, ROWS / 128, 1), 256, GEMM_TC_SMEM>>>(
            xng, 64, 0, wTg, 64, 0, qkvg, 768, 0, 64, 1.0f);
        // dots = 0.125 * q0 @ k0^T (batch 0 only)
        gemm_tc_k<<<dim3(NTOK / 128, NTOK / 128, 1), 256, GEMM_TC_SMEM>>>(
            qkvg, 768, 0, qkvg + 256, 768, 0, dotsg, NTOK, 0, 256, 0.125f);
        // softmax
        if (l == 1)
            dual_softmax_k<<<NTOK, 256>>>(dotsg, Am, attng, out_attn, out_ds);
        else
            attn_softmax_k<<<NTOK, 256>>>(dotsg, Am, attng);
        // vT (both batches -> [512,4096] contiguous)
        for (int z = 0; z < BATCH; z++)
            transpose_k<<<dim3(INNERD / 32, NTOK / 32), tblk>>>(
                qkvg + (size_t)z * NTOK * 768 + 512, 768,
                vTg + (size_t)z * INNERD * NTOK, NTOK);
        // av = attn @ vT^T, split-K x2 (partials into free dots scratch)
        gemm_tc_k<<<dim3(512 / 128, NTOK / 128, 2), 256, GEMM_TC_SMEM>>>(
            attng, NTOK, 2048, vTg, NTOK, 2048, dotsg, 512, avHalf, 2048, 1.0f);
        add2_k<<<(int)(avHalf / 4 + 255) / 256, 256>>>(dotsg, dotsg + avHalf, avg, (int)(avHalf / 4));
        // x[z] = xn[z] + (av[:, z-half] @ Wout[l] + bout[l])  — one z-batched launch
        gemm_k<<<dim3(1, NTOK / 64, 2), blk>>>(
            avg, 512, (size_t)INNERD, Wout + (size_t)l * INNERD * 64, 64,
            xg, 64, (size_t)NTOK * 64, INNERD,
            bout + l * 64, xng, 64, (size_t)NTOK * 64, 0);
        // xm = LN(x)
        ln_k<<<ROWS / 8, 256>>>(xg, g2 + l * 64, b2 + l * 64, xng, ROWS);
        // h = gelu(xm @ W1 + bb1)
        gemm_k<<<dim3(1, ROWS / 64, 1), blk>>>(
            xng, 64, 0, W1 + (size_t)l * 64 * 64, 64, qkvg, 64, 0, 64,
            bb1 + l * 64, nullptr, 64, 0, 1);
        // x = xm + (h @ W2 + bb2)
        gemm_k<<<dim3(1, ROWS / 64, 1), blk>>>(
            qkvg, 64, 0, W2 + (size_t)l * 64 * 64, 64, xg, 64, 0, 64,
            bb2 + l * 64, xng, 64, 0, 0);
    }
    // final LN -> output
    ln_k<<<ROWS / 8, 256>>>(xg, gf, bf, out_x, ROWS);
}

// round 11
// speedup vs baseline: 1.4171x; 1.4171x over previous
#include <cuda_runtime.h>
#include <math.h>
#include <stdint.h>

#define NTOK   4096
#define BATCH  2
#define DIM64  64
#define INNERD 256
#define ROWS   (BATCH * NTOK)   // 8192

// -------------------- device scratch --------------------
__device__ float g_xn  [ROWS * DIM64];
__device__ float g_x   [ROWS * DIM64];
__device__ float g_qkv [ROWS * INNERD * 3];
__device__ float g_dots[(size_t)NTOK * NTOK];     // reused as split-K partials after softmax
__device__ float g_attn[(size_t)NTOK * NTOK];
__device__ float g_vT  [BATCH * INNERD * NTOK];   // [512][4096]
__device__ float g_wT  [768 * 64];

// -------------------- helpers --------------------
__device__ __forceinline__ void mma_tf32(float c[4], const float a[4], const float b[2]) {
    asm volatile(
        "mma.sync.aligned.m16n8k8.row.col.f32.tf32.tf32.f32 "
        "{%0,%1,%2,%3}, {%4,%5,%6,%7}, {%8,%9}, {%0,%1,%2,%3};"
        : "+f"(c[0]), "+f"(c[1]), "+f"(c[2]), "+f"(c[3])
        : "r"(__float_as_uint(a[0])), "r"(__float_as_uint(a[1])),
          "r"(__float_as_uint(a[2])), "r"(__float_as_uint(a[3])),
          "r"(__float_as_uint(b[0])), "r"(__float_as_uint(b[1])));
}

__device__ __forceinline__ void cp16(uint32_t dst, const void* src) {
    asm volatile("cp.async.cg.shared.global [%0], [%1], 16;" :: "r"(dst), "l"(src));
}

// ==================== TF32 tensor-core NT GEMM ====================
// 4 warps (128 thr), CTA tile 128x128, warp tile 64x64 (2x2 warp grid),
// BK=32, 2-stage cp.async, scalar-LDS fragments (1.0 LDS/MMA), 2 CTAs/SM.
// C[z] = alpha * A[z](M,K) * B[z](N,K)^T ; M,N mult of 128, K mult of 32.
// z strides are ELEMENT offsets (doubles as K-offset for split-K).
#define SPITCH 36
#define ASTG   (128 * SPITCH)
#define AS(p, m, k) sm[(p) * ASTG + (m) * SPITCH + (k)]
#define BS(p, n, k) sm[(2 + (p)) * ASTG + (n) * SPITCH + (k)]
#define GEMM_TC_SMEM (4 * ASTG * (int)sizeof(float))   // 73728 bytes

__global__ void __launch_bounds__(128, 2)
gemm_tc_k(const float* __restrict__ A, int lda, size_t sAz,
          const float* __restrict__ B, int ldb, size_t sBz,
          float* __restrict__ C, int ldc, size_t sCz,
          int K, float alpha)
{
    extern __shared__ float sm[];
    const uint32_t smb = (uint32_t)__cvta_generic_to_shared(sm);
    const int tid  = threadIdx.x;
    const int wid  = tid >> 5, lane = tid & 31;
    const int wm   = wid & 1,  wn   = wid >> 1;
    const int gid  = lane >> 2, tig = lane & 3;
    const int m0   = blockIdx.y * 128, n0 = blockIdx.x * 128;

    A += (size_t)blockIdx.z * sAz;
    B += (size_t)blockIdx.z * sBz;
    C += (size_t)blockIdx.z * sCz;

    int lrow[8], lkq[8];
    #pragma unroll
    for (int i = 0; i < 8; i++) {
        int c = tid + i * 128;
        lrow[i] = c >> 3;
        lkq[i]  = (c & 7) << 2;
    }

#define ISSUE(s, kt)                                                                     \
    {                                                                                    \
        const int _k0 = (kt) << 5;                                                       \
        _Pragma("unroll")                                                                \
        for (int i = 0; i < 8; i++) {                                                    \
            cp16(smb + (uint32_t)((((s) * ASTG) + lrow[i] * SPITCH + lkq[i]) * 4),       \
                 A + (size_t)(m0 + lrow[i]) * lda + _k0 + lkq[i]);                       \
            cp16(smb + (uint32_t)((((2 + (s)) * ASTG) + lrow[i] * SPITCH + lkq[i]) * 4), \
                 B + (size_t)(n0 + lrow[i]) * ldb + _k0 + lkq[i]);                       \
        }                                                                                \
        asm volatile("cp.async.commit_group;");                                         \
    }

    float acc[4][8][4];
    #pragma unroll
    for (int mt = 0; mt < 4; mt++)
        #pragma unroll
        for (int nt = 0; nt < 8; nt++)
            #pragma unroll
            for (int q = 0; q < 4; q++) acc[mt][nt][q] = 0.0f;

    const int KT = K >> 5;
    ISSUE(0, 0);

    for (int kt = 0; kt < KT; kt++) {
        const int p = kt & 1;
        if (kt + 1 < KT) {
            ISSUE(p ^ 1, kt + 1);
            asm volatile("cp.async.wait_group 1;");
        } else {
            asm volatile("cp.async.wait_group 0;");
        }
        __syncthreads();

        #pragma unroll
        for (int ks = 0; ks < 4; ks++) {
            const int kb = ks << 3;
            float fa[4][4];
            float fb[8][2];
            #pragma unroll
            for (int mt = 0; mt < 4; mt++) {
                const int mr = wm * 64 + mt * 16 + gid;
                fa[mt][0] = AS(p, mr,     kb + tig);
                fa[mt][1] = AS(p, mr + 8, kb + tig);
                fa[mt][2] = AS(p, mr,     kb + tig + 4);
                fa[mt][3] = AS(p, mr + 8, kb + tig + 4);
            }
            #pragma unroll
            for (int nt = 0; nt < 8; nt++) {
                const int nr = wn * 64 + nt * 8 + gid;
                fb[nt][0] = BS(p, nr, kb + tig);
                fb[nt][1] = BS(p, nr, kb + tig + 4);
            }
            #pragma unroll
            for (int nt = 0; nt < 8; nt++)
                #pragma unroll
                for (int mt = 0; mt < 4; mt++)
                    mma_tf32(acc[mt][nt], fa[mt], fb[nt]);
        }
        __syncthreads();
    }

    // epilogue
    #pragma unroll
    for (int mt = 0; mt < 4; mt++) {
        const int row = m0 + wm * 64 + mt * 16 + gid;
        #pragma unroll
        for (int nt = 0; nt < 8; nt++) {
            const int col = n0 + wn * 64 + nt * 8 + tig * 2;
            float2 v0 = make_float2(acc[mt][nt][0] * alpha, acc[mt][nt][1] * alpha);
            float2 v1 = make_float2(acc[mt][nt][2] * alpha, acc[mt][nt][3] * alpha);
            *(float2*)(C + (size_t)row * ldc + col)       = v0;
            *(float2*)(C + (size_t)(row + 8) * ldc + col) = v1;
        }
    }
#undef ISSUE
}

// -------------------- 32x32 transpose --------------------
__global__ void transpose_k(const float* __restrict__ src, int lds,
                            float* __restrict__ dst, int ldd)
{
    __shared__ float t[32][33];
    int c0 = blockIdx.x * 32, r0 = blockIdx.y * 32;
    int tx = threadIdx.x, ty = threadIdx.y;
    #pragma unroll
    for (int j = 0; j < 32; j += 8)
        t[ty + j][tx] = src[(size_t)(r0 + ty + j) * lds + c0 + tx];
    __syncthreads();
    #pragma unroll
    for (int j = 0; j < 32; j += 8)
        dst[(size_t)(c0 + ty + j) * ldd + r0 + tx] = t[tx][ty + j];
}

// -------------------- LayerNorm (dim 64) --------------------
__global__ void ln_k(const float* __restrict__ x, const float* __restrict__ g,
                     const float* __restrict__ b, float* __restrict__ y, int rows)
{
    int w    = blockIdx.x * 8 + (threadIdx.x >> 5);
    int lane = threadIdx.x & 31;
    if (w >= rows) return;
    const float* xr = x + (size_t)w * 64;
    float v0 = xr[lane], v1 = xr[lane + 32];
    float s = v0 + v1;
    #pragma unroll
    for (int o = 16; o > 0; o >>= 1) s += __shfl_xor_sync(0xffffffffu, s, o);
    float m  = s * (1.0f / 64.0f);
    float d0 = v0 - m, d1 = v1 - m;
    float q  = d0 * d0 + d1 * d1;
    #pragma unroll
    for (int o = 16; o > 0; o >>= 1) q += __shfl_xor_sync(0xffffffffu, q, o);
    float inv = rsqrtf(q * (1.0f / 64.0f) + 1e-5f);
    float* yr = y + (size_t)w * 64;
    yr[lane]      = d0 * inv * g[lane]      + b[lane];
    yr[lane + 32] = d1 * inv * g[lane + 32] + b[lane + 32];
}

// ---- small fp32 GEMM (N=64 projections). Optional A2: A-tile = A + A2 (split-K fuse) ----
__global__ void __launch_bounds__(256)
gemm_k(const float* __restrict__ A, const float* __restrict__ A2, int lda, size_t sAz,
       const float* __restrict__ B, int ldb,
       float* __restrict__ C, int ldc, size_t sCz,
       int K,
       const float* __restrict__ bias,
       const float* __restrict__ resid, int ldr, size_t sRz,
       int do_gelu)
{
    __shared__ float As[16][68];
    __shared__ float Bs[16][68];
    int tx = threadIdx.x, ty = threadIdx.y;
    int t  = ty * 16 + tx;
    int m0 = blockIdx.y * 64, n0 = blockIdx.x * 64;

    A += (size_t)blockIdx.z * sAz;
    if (A2) A2 += (size_t)blockIdx.z * sAz;
    C += (size_t)blockIdx.z * sCz;
    if (resid) resid += (size_t)blockIdx.z * sRz;

    float acc[4][4] = {};
    int ar  = t / 4;
    int ac4 = (t % 4) * 4;
    int br  = t / 16;
    int bc4 = (t % 16) * 4;

    for (int k0 = 0; k0 < K; k0 += 16) {
        const size_t aoff = (size_t)(m0 + ar) * lda + k0 + ac4;
        if (A2) {
            #pragma unroll
            for (int q = 0; q < 4; q++) As[ac4 + q][ar] = A[aoff + q] + A2[aoff + q];
        } else {
            #pragma unroll
            for (int q = 0; q < 4; q++) As[ac4 + q][ar] = A[aoff + q];
        }
        const float* Bp = B + (size_t)(k0 + br) * ldb + n0 + bc4;
        #pragma unroll
        for (int q = 0; q < 4; q++) Bs[br][bc4 + q] = Bp[q];
        __syncthreads();
        #pragma unroll
        for (int kk = 0; kk < 16; kk++) {
            float a[4], b[4];
            #pragma unroll
            for (int i = 0; i < 4; i++) a[i] = As[kk][ty * 4 + i];
            #pragma unroll
            for (int j = 0; j < 4; j++) b[j] = Bs[kk][tx * 4 + j];
            #pragma unroll
            for (int i = 0; i < 4; i++)
                #pragma unroll
                for (int j = 0; j < 4; j++)
                    acc[i][j] = fmaf(a[i], b[j], acc[i][j]);
        }
        __syncthreads();
    }

    #pragma unroll
    for (int i = 0; i < 4; i++) {
        int row = m0 + ty * 4 + i;
        #pragma unroll
        for (int j = 0; j < 4; j++) {
            int col = n0 + tx * 4 + j;
            float v = acc[i][j];
            if (bias)    v += bias[col];
            if (do_gelu) v = 0.5f * v * (1.0f + erff(v * 0.70710678118654752f));
            if (resid)   v += resid[(size_t)row * ldr + col];
            C[(size_t)row * ldc + col] = v;
        }
    }
}

// -------------------- block reductions --------------------
__device__ __forceinline__ float blk_max(float v, float* wred, int wid, int lane) {
    #pragma unroll
    for (int o = 16; o > 0; o >>= 1) v = fmaxf(v, __shfl_xor_sync(0xffffffffu, v, o));
    if (lane == 0) wred[wid] = v;
    __syncthreads();
    float r = wred[0];
    #pragma unroll
    for (int i = 1; i < 8; i++) r = fmaxf(r, wred[i]);
    __syncthreads();
    return r;
}
__device__ __forceinline__ float blk_sum(float v, float* wred, int wid, int lane) {
    #pragma unroll
    for (int o = 16; o > 0; o >>= 1) v += __shfl_xor_sync(0xffffffffu, v, o);
    if (lane == 0) wred[wid] = v;
    __syncthreads();
    float r = 0.0f;
    #pragma unroll
    for (int i = 0; i < 8; i++) r += wred[i];
    __syncthreads();
    return r;
}

// -------------------- masked softmax, register-resident --------------------
__global__ void attn_softmax_k(const float* __restrict__ dots, const float* __restrict__ Am,
                               float* __restrict__ attn)
{
    __shared__ float wred[8];
    const int row = blockIdx.x, tid = threadIdx.x;
    const int wid = tid >> 5, lane = tid & 31;
    const float4* dr = (const float4*)(dots + (size_t)row * NTOK);
    const float4* ar = (const float4*)(Am   + (size_t)row * NTOK);
    const int dj = row >> 2, dl = row & 3;

    float4 r[4];
    float mx = -3.4e38f;
    #pragma unroll
    for (int i = 0; i < 4; i++) {
        int j = tid + i * 256;
        float4 d = dr[j], a = ar[j], v;
        v.x = (a.x > 0.0f) ? d.x : -9e15f;
        v.y = (a.y > 0.0f) ? d.y : -9e15f;
        v.z = (a.z > 0.0f) ? d.z : -9e15f;
        v.w = (a.w > 0.0f) ? d.w : -9e15f;
        if (j == dj) ((float*)&v)[dl] = 1.0f;
        r[i] = v;
        mx = fmaxf(fmaxf(fmaxf(mx, v.x), v.y), fmaxf(v.z, v.w));
    }
    mx = blk_max(mx, wred, wid, lane);

    float sum = 0.0f;
    #pragma unroll
    for (int i = 0; i < 4; i++) {
        r[i].x = __expf(r[i].x - mx); r[i].y = __expf(r[i].y - mx);
        r[i].z = __expf(r[i].z - mx); r[i].w = __expf(r[i].w - mx);
        sum += (r[i].x + r[i].y) + (r[i].z + r[i].w);
    }
    sum = blk_sum(sum, wred, wid, lane);
    float inv = 1.0f / sum;

    float4* o1 = (float4*)(attn + (size_t)row * NTOK);
    #pragma unroll
    for (int i = 0; i < 4; i++) {
        int j = tid + i * 256;
        o1[j] = make_float4(r[i].x * inv, r[i].y * inv, r[i].z * inv, r[i].w * inv);
    }
}

// ----- last layer: masked softmax (attn + attn_out) AND plain softmax (ds_out) -----
__global__ void dual_softmax_k(const float* __restrict__ dots, const float* __restrict__ Am,
                               float* __restrict__ attn, float* __restrict__ attn_out,
                               float* __restrict__ ds_out)
{
    __shared__ float wred[8];
    const int row = blockIdx.x, tid = threadIdx.x;
    const int wid = tid >> 5, lane = tid & 31;
    const float4* dr = (const float4*)(dots + (size_t)row * NTOK);
    const float4* ar = (const float4*)(Am   + (size_t)row * NTOK);
    const int dj = row >> 2, dl = row & 3;

    float4 rv[4], mv[4];
    float mxr = -3.4e38f, mxm = -3.4e38f;
    #pragma unroll
    for (int i = 0; i < 4; i++) {
        int j = tid + i * 256;
        float4 d = dr[j], a = ar[j], v;
        v.x = (a.x > 0.0f) ? d.x : -9e15f;
        v.y = (a.y > 0.0f) ? d.y : -9e15f;
        v.z = (a.z > 0.0f) ? d.z : -9e15f;
        v.w = (a.w > 0.0f) ? d.w : -9e15f;
        if (j == dj) ((float*)&v)[dl] = 1.0f;
        rv[i] = d; mv[i] = v;
        mxr = fmaxf(fmaxf(fmaxf(mxr, d.x), d.y), fmaxf(d.z, d.w));
        mxm = fmaxf(fmaxf(fmaxf(mxm, v.x), v.y), fmaxf(v.z, v.w));
    }
    mxm = blk_max(mxm, wred, wid, lane);
    mxr = blk_max(mxr, wred, wid, lane);

    float sm = 0.0f, sr = 0.0f;
    #pragma unroll
    for (int i = 0; i < 4; i++) {
        mv[i].x = __expf(mv[i].x - mxm); mv[i].y = __expf(mv[i].y - mxm);
        mv[i].z = __expf(mv[i].z - mxm); mv[i].w = __expf(mv[i].w - mxm);
        rv[i].x = __expf(rv[i].x - mxr); rv[i].y = __expf(rv[i].y - mxr);
        rv[i].z = __expf(rv[i].z - mxr); rv[i].w = __expf(rv[i].w - mxr);
        sm += (mv[i].x + mv[i].y) + (mv[i].z + mv[i].w);
        sr += (rv[i].x + rv[i].y) + (rv[i].z + rv[i].w);
    }
    sm = blk_sum(sm, wred, wid, lane);
    sr = blk_sum(sr, wred, wid, lane);
    float invm = 1.0f / sm, invr = 1.0f / sr;

    float4* o1 = (float4*)(attn     + (size_t)row * NTOK);
    float4* o2 = (float4*)(attn_out + (size_t)row * NTOK);
    float4* o3 = (float4*)(ds_out   + (size_t)row * NTOK);
    #pragma unroll
    for (int i = 0; i < 4; i++) {
        int j = tid + i * 256;
        float4 vo = make_float4(mv[i].x * invm, mv[i].y * invm, mv[i].z * invm, mv[i].w * invm);
        o1[j] = vo; o2[j] = vo;
        o3[j] = make_float4(rv[i].x * invr, rv[i].y * invr, rv[i].z * invr, rv[i].w * invr);
    }
}

// -------------------- host orchestration --------------------
extern "C" void kernel_launch(void* const* d_in, const int* in_sizes, int n_in,
                              void* d_out, int out_size)
{
    const float* embed = (const float*)d_in[0];
    const float* Am    = (const float*)d_in[1];
    const float* g1    = (const float*)d_in[2];
    const float* b1    = (const float*)d_in[3];
    const float* Wqkv  = (const float*)d_in[4];
    const float* Wout  = (const float*)d_in[5];
    const float* bout  = (const float*)d_in[6];
    const float* g2    = (const float*)d_in[7];
    const float* b2    = (const float*)d_in[8];
    const float* W1    = (const float*)d_in[9];
    const float* bb1   = (const float*)d_in[10];
    const float* W2    = (const float*)d_in[11];
    const float* bb2   = (const float*)d_in[12];
    const float* gf    = (const float*)d_in[13];
    const float* bf    = (const float*)d_in[14];

    float *xg, *xng, *qkvg, *dotsg, *attng, *vTg, *wTg;
    cudaGetSymbolAddress((void**)&xg,    g_x);
    cudaGetSymbolAddress((void**)&xng,   g_xn);
    cudaGetSymbolAddress((void**)&qkvg,  g_qkv);
    cudaGetSymbolAddress((void**)&dotsg, g_dots);
    cudaGetSymbolAddress((void**)&attng, g_attn);
    cudaGetSymbolAddress((void**)&vTg,   g_vT);
    cudaGetSymbolAddress((void**)&wTg,   g_wT);

    cudaFuncSetAttribute(gemm_tc_k, cudaFuncAttributeMaxDynamicSharedMemorySize, GEMM_TC_SMEM);

    float* out_x    = (float*)d_out;
    float* out_attn = out_x + (size_t)ROWS * DIM64;
    float* out_ds   = out_attn + (size_t)NTOK * NTOK;

    dim3 blk(16, 16);
    dim3 tblk(32, 8);
    const size_t avHalf = (size_t)NTOK * 512;   // split-K partial stride (in g_dots)

    for (int l = 0; l < 2; l++) {
        const float* src = l ? xg : embed;
        // xn = LN(x)
        ln_k<<<ROWS / 8, 256>>>(src, g1 + l * 64, b1 + l * 64, xng, ROWS);
        // wT = Wqkv[l]^T
        transpose_k<<<dim3(768 / 32, 64 / 32), tblk>>>(Wqkv + (size_t)l * 64 * 768, 768, wTg, 64);
        // qkv = xn @ Wqkv[l] (NT): [8192,64] x [768,64]^T
        gemm_tc_k<<<dim3(768 / 128, ROWS / 128, 1), 128, GEMM_TC_SMEM>>>(
            xng, 64, 0, wTg, 64, 0, qkvg, 768, 0, 64, 1.0f);
        // dots = 0.125 * q0 @ k0^T (batch 0 only)
        gemm_tc_k<<<dim3(NTOK / 128, NTOK / 128, 1), 128, GEMM_TC_SMEM>>>(
            qkvg, 768, 0, qkvg + 256, 768, 0, dotsg, NTOK, 0, 256, 0.125f);
        // softmax
        if (l == 1)
            dual_softmax_k<<<NTOK, 256>>>(dotsg, Am, attng, out_attn, out_ds);
        else
            attn_softmax_k<<<NTOK, 256>>>(dotsg, Am, attng);
        // vT (both batches -> [512,4096] contiguous)
        for (int z = 0; z < BATCH; z++)
            transpose_k<<<dim3(INNERD / 32, NTOK / 32), tblk>>>(
                qkvg + (size_t)z * NTOK * 768 + 512, 768,
                vTg + (size_t)z * INNERD * NTOK, NTOK);
        // av = attn @ vT^T, split-K x2 (partials into free dots scratch)
        gemm_tc_k<<<dim3(512 / 128, NTOK / 128, 2), 128, GEMM_TC_SMEM>>>(
            attng, NTOK, 2048, vTg, NTOK, 2048, dotsg, 512, avHalf, 2048, 1.0f);
        // x[z] = xn[z] + ((p0+p1)[:, z*256..] @ Wout[l] + bout[l]) — split-K add fused
        gemm_k<<<dim3(1, NTOK / 64, 2), blk>>>(
            dotsg, dotsg + avHalf, 512, (size_t)INNERD,
            Wout + (size_t)l * INNERD * 64, 64,
            xg, 64, (size_t)NTOK * 64, INNERD,
            bout + l * 64, xng, 64, (size_t)NTOK * 64, 0);
        // xm = LN(x)
        ln_k<<<ROWS / 8, 256>>>(xg, g2 + l * 64, b2 + l * 64, xng, ROWS);
        // h = gelu(xm @ W1 + bb1)
        gemm_k<<<dim3(1, ROWS / 64, 1), blk>>>(
            xng, nullptr, 64, 0, W1 + (size_t)l * 64 * 64, 64, qkvg, 64, 0, 64,
            bb1 + l * 64, nullptr, 64, 0, 1);
        // x = xm + (h @ W2 + bb2)
        gemm_k<<<dim3(1, ROWS / 64, 1), blk>>>(
            qkvg, nullptr, 64, 0, W2 + (size_t)l * 64 * 64, 64, xg, 64, 0, 64,
            bb2 + l * 64, xng, 64, 0, 0);
    }
    // final LN -> output
    ln_k<<<ROWS / 8, 256>>>(xg, gf, bf, out_x, ROWS);
}

// round 13
// speedup vs baseline: 1.4699x; 1.0372x over previous
#include <cuda_runtime.h>
#include <math.h>
#include <stdint.h>

#define NTOK   4096
#define BATCH  2
#define DIM64  64
#define INNERD 256
#define ROWS   (BATCH * NTOK)   // 8192

// -------------------- device scratch --------------------
__device__ float g_xn  [ROWS * DIM64];
__device__ float g_x   [ROWS * DIM64];
__device__ float g_qkv [ROWS * INNERD * 3];
__device__ float g_dots[(size_t)NTOK * NTOK];       // reused as split-K partials after softmax
__device__ float g_attn[(size_t)NTOK * NTOK];
__device__ float g_vT  [BATCH * INNERD * NTOK];     // [512][4096]
__device__ float g_wT  [768 * 64];
__device__ uint32_t g_mask[NTOK * 128];             // adjacency bitmask, built in layer 0

// -------------------- helpers --------------------
__device__ __forceinline__ void mma_tf32(float c[4], const float a[4], const float b[2]) {
    asm volatile(
        "mma.sync.aligned.m16n8k8.row.col.f32.tf32.tf32.f32 "
        "{%0,%1,%2,%3}, {%4,%5,%6,%7}, {%8,%9}, {%0,%1,%2,%3};"
        : "+f"(c[0]), "+f"(c[1]), "+f"(c[2]), "+f"(c[3])
        : "r"(__float_as_uint(a[0])), "r"(__float_as_uint(a[1])),
          "r"(__float_as_uint(a[2])), "r"(__float_as_uint(a[3])),
          "r"(__float_as_uint(b[0])), "r"(__float_as_uint(b[1])));
}

__device__ __forceinline__ void cp16(uint32_t dst, const void* src) {
    asm volatile("cp.async.cg.shared.global [%0], [%1], 16;" :: "r"(dst), "l"(src));
}

// ==================== TF32 tensor-core NT GEMM (unchanged from R11: 140 TF/s) ============
#define SPITCH 36
#define ASTG   (128 * SPITCH)
#define AS(p, m, k) sm[(p) * ASTG + (m) * SPITCH + (k)]
#define BS(p, n, k) sm[(2 + (p)) * ASTG + (n) * SPITCH + (k)]
#define GEMM_TC_SMEM (4 * ASTG * (int)sizeof(float))   // 73728 bytes

__global__ void __launch_bounds__(128, 2)
gemm_tc_k(const float* __restrict__ A, int lda, size_t sAz,
          const float* __restrict__ B, int ldb, size_t sBz,
          float* __restrict__ C, int ldc, size_t sCz,
          int K, float alpha)
{
    extern __shared__ float sm[];
    const uint32_t smb = (uint32_t)__cvta_generic_to_shared(sm);
    const int tid  = threadIdx.x;
    const int wid  = tid >> 5, lane = tid & 31;
    const int wm   = wid & 1,  wn   = wid >> 1;
    const int gid  = lane >> 2, tig = lane & 3;
    const int m0   = blockIdx.y * 128, n0 = blockIdx.x * 128;

    A += (size_t)blockIdx.z * sAz;
    B += (size_t)blockIdx.z * sBz;
    C += (size_t)blockIdx.z * sCz;

    int lrow[8], lkq[8];
    #pragma unroll
    for (int i = 0; i < 8; i++) {
        int c = tid + i * 128;
        lrow[i] = c >> 3;
        lkq[i]  = (c & 7) << 2;
    }

#define ISSUE(s, kt)                                                                     \
    {                                                                                    \
        const int _k0 = (kt) << 5;                                                       \
        _Pragma("unroll")                                                                \
        for (int i = 0; i < 8; i++) {                                                    \
            cp16(smb + (uint32_t)((((s) * ASTG) + lrow[i] * SPITCH + lkq[i]) * 4),       \
                 A + (size_t)(m0 + lrow[i]) * lda + _k0 + lkq[i]);                       \
            cp16(smb + (uint32_t)((((2 + (s)) * ASTG) + lrow[i] * SPITCH + lkq[i]) * 4), \
                 B + (size_t)(n0 + lrow[i]) * ldb + _k0 + lkq[i]);                       \
        }                                                                                \
        asm volatile("cp.async.commit_group;");                                         \
    }

    float acc[4][8][4];
    #pragma unroll
    for (int mt = 0; mt < 4; mt++)
        #pragma unroll
        for (int nt = 0; nt < 8; nt++)
            #pragma unroll
            for (int q = 0; q < 4; q++) acc[mt][nt][q] = 0.0f;

    const int KT = K >> 5;
    ISSUE(0, 0);

    for (int kt = 0; kt < KT; kt++) {
        const int p = kt & 1;
        if (kt + 1 < KT) {
            ISSUE(p ^ 1, kt + 1);
            asm volatile("cp.async.wait_group 1;");
        } else {
            asm volatile("cp.async.wait_group 0;");
        }
        __syncthreads();

        #pragma unroll
        for (int ks = 0; ks < 4; ks++) {
            const int kb = ks << 3;
            float fa[4][4];
            float fb[8][2];
            #pragma unroll
            for (int mt = 0; mt < 4; mt++) {
                const int mr = wm * 64 + mt * 16 + gid;
                fa[mt][0] = AS(p, mr,     kb + tig);
                fa[mt][1] = AS(p, mr + 8, kb + tig);
                fa[mt][2] = AS(p, mr,     kb + tig + 4);
                fa[mt][3] = AS(p, mr + 8, kb + tig + 4);
            }
            #pragma unroll
            for (int nt = 0; nt < 8; nt++) {
                const int nr = wn * 64 + nt * 8 + gid;
                fb[nt][0] = BS(p, nr, kb + tig);
                fb[nt][1] = BS(p, nr, kb + tig + 4);
            }
            #pragma unroll
            for (int nt = 0; nt < 8; nt++)
                #pragma unroll
                for (int mt = 0; mt < 4; mt++)
                    mma_tf32(acc[mt][nt], fa[mt], fb[nt]);
        }
        __syncthreads();
    }

    #pragma unroll
    for (int mt = 0; mt < 4; mt++) {
        const int row = m0 + wm * 64 + mt * 16 + gid;
        #pragma unroll
        for (int nt = 0; nt < 8; nt++) {
            const int col = n0 + wn * 64 + nt * 8 + tig * 2;
            float2 v0 = make_float2(acc[mt][nt][0] * alpha, acc[mt][nt][1] * alpha);
            float2 v1 = make_float2(acc[mt][nt][2] * alpha, acc[mt][nt][3] * alpha);
            *(float2*)(C + (size_t)row * ldc + col)       = v0;
            *(float2*)(C + (size_t)(row + 8) * ldc + col) = v1;
        }
    }
#undef ISSUE
}

// -------------------- 32x32 transpose (z-batched) --------------------
__global__ void transpose_k(const float* __restrict__ src, int lds, size_t sSz,
                            float* __restrict__ dst, int ldd, size_t sDz)
{
    __shared__ float t[32][33];
    src += (size_t)blockIdx.z * sSz;
    dst += (size_t)blockIdx.z * sDz;
    int c0 = blockIdx.x * 32, r0 = blockIdx.y * 32;
    int tx = threadIdx.x, ty = threadIdx.y;
    #pragma unroll
    for (int j = 0; j < 32; j += 8)
        t[ty + j][tx] = src[(size_t)(r0 + ty + j) * lds + c0 + tx];
    __syncthreads();
    #pragma unroll
    for (int j = 0; j < 32; j += 8)
        dst[(size_t)(c0 + ty + j) * ldd + r0 + tx] = t[tx][ty + j];
}

// -------------------- LayerNorm (dim 64) --------------------
__global__ void ln_k(const float* __restrict__ x, const float* __restrict__ g,
                     const float* __restrict__ b, float* __restrict__ y, int rows)
{
    int w    = blockIdx.x * 8 + (threadIdx.x >> 5);
    int lane = threadIdx.x & 31;
    if (w >= rows) return;
    const float* xr = x + (size_t)w * 64;
    float v0 = xr[lane], v1 = xr[lane + 32];
    float s = v0 + v1;
    #pragma unroll
    for (int o = 16; o > 0; o >>= 1) s += __shfl_xor_sync(0xffffffffu, s, o);
    float m  = s * (1.0f / 64.0f);
    float d0 = v0 - m, d1 = v1 - m;
    float q  = d0 * d0 + d1 * d1;
    #pragma unroll
    for (int o = 16; o > 0; o >>= 1) q += __shfl_xor_sync(0xffffffffu, q, o);
    float inv = rsqrtf(q * (1.0f / 64.0f) + 1e-5f);
    float* yr = y + (size_t)w * 64;
    yr[lane]      = d0 * inv * g[lane]      + b[lane];
    yr[lane + 32] = d1 * inv * g[lane + 32] + b[lane + 32];
}

// ---- small fp32 GEMM (N=64 projections). Optional A2: A-tile = A + A2 (split-K fuse) ----
__global__ void __launch_bounds__(256)
gemm_k(const float* __restrict__ A, const float* __restrict__ A2, int lda, size_t sAz,
       const float* __restrict__ B, int ldb,
       float* __restrict__ C, int ldc, size_t sCz,
       int K,
       const float* __restrict__ bias,
       const float* __restrict__ resid, int ldr, size_t sRz,
       int do_gelu)
{
    __shared__ float As[16][68];
    __shared__ float Bs[16][68];
    int tx = threadIdx.x, ty = threadIdx.y;
    int t  = ty * 16 + tx;
    int m0 = blockIdx.y * 64, n0 = blockIdx.x * 64;

    A += (size_t)blockIdx.z * sAz;
    if (A2) A2 += (size_t)blockIdx.z * sAz;
    C += (size_t)blockIdx.z * sCz;
    if (resid) resid += (size_t)blockIdx.z * sRz;

    float acc[4][4] = {};
    int ar  = t / 4;
    int ac4 = (t % 4) * 4;
    int br  = t / 16;
    int bc4 = (t % 16) * 4;

    for (int k0 = 0; k0 < K; k0 += 16) {
        const size_t aoff = (size_t)(m0 + ar) * lda + k0 + ac4;
        if (A2) {
            #pragma unroll
            for (int q = 0; q < 4; q++) As[ac4 + q][ar] = A[aoff + q] + A2[aoff + q];
        } else {
            #pragma unroll
            for (int q = 0; q < 4; q++) As[ac4 + q][ar] = A[aoff + q];
        }
        const float* Bp = B + (size_t)(k0 + br) * ldb + n0 + bc4;
        #pragma unroll
        for (int q = 0; q < 4; q++) Bs[br][bc4 + q] = Bp[q];
        __syncthreads();
        #pragma unroll
        for (int kk = 0; kk < 16; kk++) {
            float a[4], b[4];
            #pragma unroll
            for (int i = 0; i < 4; i++) a[i] = As[kk][ty * 4 + i];
            #pragma unroll
            for (int j = 0; j < 4; j++) b[j] = Bs[kk][tx * 4 + j];
            #pragma unroll
            for (int i = 0; i < 4; i++)
                #pragma unroll
                for (int j = 0; j < 4; j++)
                    acc[i][j] = fmaf(a[i], b[j], acc[i][j]);
        }
        __syncthreads();
    }

    #pragma unroll
    for (int i = 0; i < 4; i++) {
        int row = m0 + ty * 4 + i;
        #pragma unroll
        for (int j = 0; j < 4; j++) {
            int col = n0 + tx * 4 + j;
            float v = acc[i][j];
            if (bias)    v += bias[col];
            if (do_gelu) v = 0.5f * v * (1.0f + erff(v * 0.70710678118654752f));
            if (resid)   v += resid[(size_t)row * ldr + col];
            C[(size_t)row * ldc + col] = v;
        }
    }
}

// -------------------- block reductions --------------------
__device__ __forceinline__ float blk_max(float v, float* wred, int wid, int lane) {
    #pragma unroll
    for (int o = 16; o > 0; o >>= 1) v = fmaxf(v, __shfl_xor_sync(0xffffffffu, v, o));
    if (lane == 0) wred[wid] = v;
    __syncthreads();
    float r = wred[0];
    #pragma unroll
    for (int i = 1; i < 8; i++) r = fmaxf(r, wred[i]);
    __syncthreads();
    return r;
}
__device__ __forceinline__ float blk_sum(float v, float* wred, int wid, int lane) {
    #pragma unroll
    for (int o = 16; o > 0; o >>= 1) v += __shfl_xor_sync(0xffffffffu, v, o);
    if (lane == 0) wred[wid] = v;
    __syncthreads();
    float r = 0.0f;
    #pragma unroll
    for (int i = 0; i < 8; i++) r += wred[i];
    __syncthreads();
    return r;
}

// ---- layer-0 masked softmax: reads fp32 A, writes attn AND the 1-bit mask ----
__global__ void attn_softmax_k(const float* __restrict__ dots, const float* __restrict__ Am,
                               float* __restrict__ attn, uint32_t* __restrict__ maskw)
{
    __shared__ float wred[8];
    __shared__ uint32_t mw[128];
    const int row = blockIdx.x, tid = threadIdx.x;
    const int wid = tid >> 5, lane = tid & 31;
    const float4* dr = (const float4*)(dots + (size_t)row * NTOK);
    const float4* ar = (const float4*)(Am   + (size_t)row * NTOK);
    const int dj = row >> 2, dl = row & 3;

    if (tid < 128) mw[tid] = 0u;
    __syncthreads();

    float4 r[4];
    float mx = -3.4e38f;
    #pragma unroll
    for (int i = 0; i < 4; i++) {
        int j = tid + i * 256;
        float4 d = dr[j], a = ar[j], v;
        uint32_t bits = 0;
        v.x = (a.x > 0.0f) ? (bits |= 1u, d.x) : -9e15f;
        v.y = (a.y > 0.0f) ? (bits |= 2u, d.y) : -9e15f;
        v.z = (a.z > 0.0f) ? (bits |= 4u, d.z) : -9e15f;
        v.w = (a.w > 0.0f) ? (bits |= 8u, d.w) : -9e15f;
        if (bits) atomicOr(&mw[j >> 3], bits << ((j & 7) * 4));
        if (j == dj) ((float*)&v)[dl] = 1.0f;
        r[i] = v;
        mx = fmaxf(fmaxf(fmaxf(mx, v.x), v.y), fmaxf(v.z, v.w));
    }
    mx = blk_max(mx, wred, wid, lane);

    float sum = 0.0f;
    #pragma unroll
    for (int i = 0; i < 4; i++) {
        r[i].x = __expf(r[i].x - mx); r[i].y = __expf(r[i].y - mx);
        r[i].z = __expf(r[i].z - mx); r[i].w = __expf(r[i].w - mx);
        sum += (r[i].x + r[i].y) + (r[i].z + r[i].w);
    }
    sum = blk_sum(sum, wred, wid, lane);
    float inv = 1.0f / sum;

    float4* o1 = (float4*)(attn + (size_t)row * NTOK);
    #pragma unroll
    for (int i = 0; i < 4; i++) {
        int j = tid + i * 256;
        o1[j] = make_float4(r[i].x * inv, r[i].y * inv, r[i].z * inv, r[i].w * inv);
    }
    __syncthreads();
    if (tid < 128) maskw[row * 128 + tid] = mw[tid];
}

// ---- layer-1: masked softmax (mask from bitmask) -> attn_out; plain softmax -> ds_out ----
__global__ void dual_softmax_k(const float* __restrict__ dots, const uint32_t* __restrict__ maskw,
                               float* __restrict__ attn_out, float* __restrict__ ds_out)
{
    __shared__ float wred[8];
    const int row = blockIdx.x, tid = threadIdx.x;
    const int wid = tid >> 5, lane = tid & 31;
    const float4* dr = (const float4*)(dots + (size_t)row * NTOK);
    const uint32_t* mrow = maskw + row * 128;
    const int dj = row >> 2, dl = row & 3;

    float4 rv[4], mv[4];
    float mxr = -3.4e38f, mxm = -3.4e38f;
    #pragma unroll
    for (int i = 0; i < 4; i++) {
        int j = tid + i * 256;
        float4 d = dr[j], v;
        uint32_t bits = mrow[j >> 3] >> ((j & 7) * 4);
        v.x = (bits & 1u) ? d.x : -9e15f;
        v.y = (bits & 2u) ? d.y : -9e15f;
        v.z = (bits & 4u) ? d.z : -9e15f;
        v.w = (bits & 8u) ? d.w : -9e15f;
        if (j == dj) ((float*)&v)[dl] = 1.0f;
        rv[i] = d; mv[i] = v;
        mxr = fmaxf(fmaxf(fmaxf(mxr, d.x), d.y), fmaxf(d.z, d.w));
        mxm = fmaxf(fmaxf(fmaxf(mxm, v.x), v.y), fmaxf(v.z, v.w));
    }
    mxm = blk_max(mxm, wred, wid, lane);
    mxr = blk_max(mxr, wred, wid, lane);

    float sm = 0.0f, sr = 0.0f;
    #pragma unroll
    for (int i = 0; i < 4; i++) {
        mv[i].x = __expf(mv[i].x - mxm); mv[i].y = __expf(mv[i].y - mxm);
        mv[i].z = __expf(mv[i].z - mxm); mv[i].w = __expf(mv[i].w - mxm);
        rv[i].x = __expf(rv[i].x - mxr); rv[i].y = __expf(rv[i].y - mxr);
        rv[i].z = __expf(rv[i].z - mxr); rv[i].w = __expf(rv[i].w - mxr);
        sm += (mv[i].x + mv[i].y) + (mv[i].z + mv[i].w);
        sr += (rv[i].x + rv[i].y) + (rv[i].z + rv[i].w);
    }
    sm = blk_sum(sm, wred, wid, lane);
    sr = blk_sum(sr, wred, wid, lane);
    float invm = 1.0f / sm, invr = 1.0f / sr;

    float4* o2 = (float4*)(attn_out + (size_t)row * NTOK);
    float4* o3 = (float4*)(ds_out   + (size_t)row * NTOK);
    #pragma unroll
    for (int i = 0; i < 4; i++) {
        int j = tid + i * 256;
        o2[j] = make_float4(mv[i].x * invm, mv[i].y * invm, mv[i].z * invm, mv[i].w * invm);
        o3[j] = make_float4(rv[i].x * invr, rv[i].y * invr, rv[i].z * invr, rv[i].w * invr);
    }
}

// -------------------- host orchestration --------------------
extern "C" void kernel_launch(void* const* d_in, const int* in_sizes, int n_in,
                              void* d_out, int out_size)
{
    const float* embed = (const float*)d_in[0];
    const float* Am    = (const float*)d_in[1];
    const float* g1    = (const float*)d_in[2];
    const float* b1    = (const float*)d_in[3];
    const float* Wqkv  = (const float*)d_in[4];
    const float* Wout  = (const float*)d_in[5];
    const float* bout  = (const float*)d_in[6];
    const float* g2    = (const float*)d_in[7];
    const float* b2    = (const float*)d_in[8];
    const float* W1    = (const float*)d_in[9];
    const float* bb1   = (const float*)d_in[10];
    const float* W2    = (const float*)d_in[11];
    const float* bb2   = (const float*)d_in[12];
    const float* gf    = (const float*)d_in[13];
    const float* bf    = (const float*)d_in[14];

    float *xg, *xng, *qkvg, *dotsg, *attng, *vTg, *wTg;
    uint32_t* maskg;
    cudaGetSymbolAddress((void**)&xg,    g_x);
    cudaGetSymbolAddress((void**)&xng,   g_xn);
    cudaGetSymbolAddress((void**)&qkvg,  g_qkv);
    cudaGetSymbolAddress((void**)&dotsg, g_dots);
    cudaGetSymbolAddress((void**)&attng, g_attn);
    cudaGetSymbolAddress((void**)&vTg,   g_vT);
    cudaGetSymbolAddress((void**)&wTg,   g_wT);
    cudaGetSymbolAddress((void**)&maskg, g_mask);

    cudaFuncSetAttribute(gemm_tc_k, cudaFuncAttributeMaxDynamicSharedMemorySize, GEMM_TC_SMEM);

    float* out_x    = (float*)d_out;
    float* out_attn = out_x + (size_t)ROWS * DIM64;
    float* out_ds   = out_attn + (size_t)NTOK * NTOK;

    dim3 blk(16, 16);
    dim3 tblk(32, 8);
    const size_t avHalf = (size_t)NTOK * 512;   // split-K partial stride (in g_dots)

    for (int l = 0; l < 2; l++) {
        const float* src = l ? xg : embed;
        // xn = LN(x)
        ln_k<<<ROWS / 8, 256>>>(src, g1 + l * 64, b1 + l * 64, xng, ROWS);
        // wT = Wqkv[l]^T
        transpose_k<<<dim3(768 / 32, 64 / 32, 1), tblk>>>(
            Wqkv + (size_t)l * 64 * 768, 768, 0, wTg, 64, 0);
        // qkv = xn @ Wqkv[l] (NT): [8192,64] x [768,64]^T
        gemm_tc_k<<<dim3(768 / 128, ROWS / 128, 1), 128, GEMM_TC_SMEM>>>(
            xng, 64, 0, wTg, 64, 0, qkvg, 768, 0, 64, 1.0f);
        // dots = 0.125 * q0 @ k0^T (batch 0 only)
        gemm_tc_k<<<dim3(NTOK / 128, NTOK / 128, 1), 128, GEMM_TC_SMEM>>>(
            qkvg, 768, 0, qkvg + 256, 768, 0, dotsg, NTOK, 0, 256, 0.125f);
        // softmax: layer 0 builds the bitmask; layer 1 consumes it and writes outputs only
        const float* attn_src;
        if (l == 0) {
            attn_softmax_k<<<NTOK, 256>>>(dotsg, Am, attng, maskg);
            attn_src = attng;
        } else {
            dual_softmax_k<<<NTOK, 256>>>(dotsg, maskg, out_attn, out_ds);
            attn_src = out_attn;
        }
        // vT (both batches, one z-batched launch -> [512,4096] contiguous)
        transpose_k<<<dim3(INNERD / 32, NTOK / 32, BATCH), tblk>>>(
            qkvg + 512, 768, (size_t)NTOK * 768,
            vTg, NTOK, (size_t)INNERD * NTOK);
        // av = attn @ vT^T, split-K x2 (partials into free dots scratch)
        gemm_tc_k<<<dim3(512 / 128, NTOK / 128, 2), 128, GEMM_TC_SMEM>>>(
            attn_src, NTOK, 2048, vTg, NTOK, 2048, dotsg, 512, avHalf, 2048, 1.0f);
        // x[z] = xn[z] + ((p0+p1)[:, z*256..] @ Wout[l] + bout[l]) — split-K add fused
        gemm_k<<<dim3(1, NTOK / 64, 2), blk>>>(
            dotsg, dotsg + avHalf, 512, (size_t)INNERD,
            Wout + (size_t)l * INNERD * 64, 64,
            xg, 64, (size_t)NTOK * 64, INNERD,
            bout + l * 64, xng, 64, (size_t)NTOK * 64, 0);
        // xm = LN(x)
        ln_k<<<ROWS / 8, 256>>>(xg, g2 + l * 64, b2 + l * 64, xng, ROWS);
        // h = gelu(xm @ W1 + bb1)
        gemm_k<<<dim3(1, ROWS / 64, 1), blk>>>(
            xng, nullptr, 64, 0, W1 + (size_t)l * 64 * 64, 64, qkvg, 64, 0, 64,
            bb1 + l * 64, nullptr, 64, 0, 1);
        // x = xm + (h @ W2 + bb2)
        gemm_k<<<dim3(1, ROWS / 64, 1), blk>>>(
            qkvg, nullptr, 64, 0, W2 + (size_t)l * 64 * 64, 64, xg, 64, 0, 64,
            bb2 + l * 64, xng, 64, 0, 0);
    }
    // final LN -> output
    ln_k<<<ROWS / 8, 256>>>(xg, gf, bf, out_x, ROWS);
}

// round 14
// speedup vs baseline: 1.8215x; 1.2392x over previous
#include <cuda_runtime.h>
#include <cuda_bf16.h>
#include <math.h>
#include <stdint.h>

#define NTOK   4096
#define BATCH  2
#define DIM64  64
#define INNERD 256
#define ROWS   (BATCH * NTOK)   // 8192

// -------------------- device scratch --------------------
__device__ float g_xn  [ROWS * DIM64];
__device__ float g_x   [ROWS * DIM64];
__device__ float g_qkv [ROWS * INNERD * 3];
__device__ float g_dots[(size_t)NTOK * NTOK];           // reused as split-K partials after softmax
__device__ __nv_bfloat16 g_attnb[(size_t)NTOK * NTOK];  // bf16 attn for the AV GEMM
__device__ __nv_bfloat16 g_vTb [BATCH * INNERD * NTOK]; // bf16 [512][4096]
__device__ float g_wT  [768 * 64];
__device__ uint32_t g_mask[NTOK * 128];                 // adjacency bitmask, built in layer 0

// -------------------- helpers --------------------
__device__ __forceinline__ void mma_tf32(float c[4], const float a[4], const float b[2]) {
    asm volatile(
        "mma.sync.aligned.m16n8k8.row.col.f32.tf32.tf32.f32 "
        "{%0,%1,%2,%3}, {%4,%5,%6,%7}, {%8,%9}, {%0,%1,%2,%3};"
        : "+f"(c[0]), "+f"(c[1]), "+f"(c[2]), "+f"(c[3])
        : "r"(__float_as_uint(a[0])), "r"(__float_as_uint(a[1])),
          "r"(__float_as_uint(a[2])), "r"(__float_as_uint(a[3])),
          "r"(__float_as_uint(b[0])), "r"(__float_as_uint(b[1])));
}

__device__ __forceinline__ void mma_bf16(float c[4], const uint32_t a[4],
                                         uint32_t b0, uint32_t b1) {
    asm volatile(
        "mma.sync.aligned.m16n8k16.row.col.f32.bf16.bf16.f32 "
        "{%0,%1,%2,%3}, {%4,%5,%6,%7}, {%8,%9}, {%0,%1,%2,%3};"
        : "+f"(c[0]), "+f"(c[1]), "+f"(c[2]), "+f"(c[3])
        : "r"(a[0]), "r"(a[1]), "r"(a[2]), "r"(a[3]), "r"(b0), "r"(b1));
}

__device__ __forceinline__ void cp16(uint32_t dst, const void* src) {
    asm volatile("cp.async.cg.shared.global [%0], [%1], 16;" :: "r"(dst), "l"(src));
}

__device__ __forceinline__ uint32_t pack_bf2(float a, float b) {
    __nv_bfloat162 h = __floats2bfloat162_rn(a, b);
    return *(uint32_t*)&h;
}

// ==================== TF32 tensor-core NT GEMM (unchanged: 140 TF/s) ============
#define SPITCH 36
#define ASTG   (128 * SPITCH)
#define AS(p, m, k) sm[(p) * ASTG + (m) * SPITCH + (k)]
#define BS(p, n, k) sm[(2 + (p)) * ASTG + (n) * SPITCH + (k)]
#define GEMM_TC_SMEM (4 * ASTG * (int)sizeof(float))   // 73728 bytes

__global__ void __launch_bounds__(128, 2)
gemm_tc_k(const float* __restrict__ A, int lda, size_t sAz,
          const float* __restrict__ B, int ldb, size_t sBz,
          float* __restrict__ C, int ldc, size_t sCz,
          int K, float alpha)
{
    extern __shared__ float sm[];
    const uint32_t smb = (uint32_t)__cvta_generic_to_shared(sm);
    const int tid  = threadIdx.x;
    const int wid  = tid >> 5, lane = tid & 31;
    const int wm   = wid & 1,  wn   = wid >> 1;
    const int gid  = lane >> 2, tig = lane & 3;
    const int m0   = blockIdx.y * 128, n0 = blockIdx.x * 128;

    A += (size_t)blockIdx.z * sAz;
    B += (size_t)blockIdx.z * sBz;
    C += (size_t)blockIdx.z * sCz;

    int lrow[8], lkq[8];
    #pragma unroll
    for (int i = 0; i < 8; i++) {
        int c = tid + i * 128;
        lrow[i] = c >> 3;
        lkq[i]  = (c & 7) << 2;
    }

#define ISSUE(s, kt)                                                                     \
    {                                                                                    \
        const int _k0 = (kt) << 5;                                                       \
        _Pragma("unroll")                                                                \
        for (int i = 0; i < 8; i++) {                                                    \
            cp16(smb + (uint32_t)((((s) * ASTG) + lrow[i] * SPITCH + lkq[i]) * 4),       \
                 A + (size_t)(m0 + lrow[i]) * lda + _k0 + lkq[i]);                       \
            cp16(smb + (uint32_t)((((2 + (s)) * ASTG) + lrow[i] * SPITCH + lkq[i]) * 4), \
                 B + (size_t)(n0 + lrow[i]) * ldb + _k0 + lkq[i]);                       \
        }                                                                                \
        asm volatile("cp.async.commit_group;");                                         \
    }

    float acc[4][8][4];
    #pragma unroll
    for (int mt = 0; mt < 4; mt++)
        #pragma unroll
        for (int nt = 0; nt < 8; nt++)
            #pragma unroll
            for (int q = 0; q < 4; q++) acc[mt][nt][q] = 0.0f;

    const int KT = K >> 5;
    ISSUE(0, 0);

    for (int kt = 0; kt < KT; kt++) {
        const int p = kt & 1;
        if (kt + 1 < KT) {
            ISSUE(p ^ 1, kt + 1);
            asm volatile("cp.async.wait_group 1;");
        } else {
            asm volatile("cp.async.wait_group 0;");
        }
        __syncthreads();

        #pragma unroll
        for (int ks = 0; ks < 4; ks++) {
            const int kb = ks << 3;
            float fa[4][4];
            float fb[8][2];
            #pragma unroll
            for (int mt = 0; mt < 4; mt++) {
                const int mr = wm * 64 + mt * 16 + gid;
                fa[mt][0] = AS(p, mr,     kb + tig);
                fa[mt][1] = AS(p, mr + 8, kb + tig);
                fa[mt][2] = AS(p, mr,     kb + tig + 4);
                fa[mt][3] = AS(p, mr + 8, kb + tig + 4);
            }
            #pragma unroll
            for (int nt = 0; nt < 8; nt++) {
                const int nr = wn * 64 + nt * 8 + gid;
                fb[nt][0] = BS(p, nr, kb + tig);
                fb[nt][1] = BS(p, nr, kb + tig + 4);
            }
            #pragma unroll
            for (int nt = 0; nt < 8; nt++)
                #pragma unroll
                for (int mt = 0; mt < 4; mt++)
                    mma_tf32(acc[mt][nt], fa[mt], fb[nt]);
        }
        __syncthreads();
    }

    #pragma unroll
    for (int mt = 0; mt < 4; mt++) {
        const int row = m0 + wm * 64 + mt * 16 + gid;
        #pragma unroll
        for (int nt = 0; nt < 8; nt++) {
            const int col = n0 + wn * 64 + nt * 8 + tig * 2;
            float2 v0 = make_float2(acc[mt][nt][0] * alpha, acc[mt][nt][1] * alpha);
            float2 v1 = make_float2(acc[mt][nt][2] * alpha, acc[mt][nt][3] * alpha);
            *(float2*)(C + (size_t)row * ldc + col)       = v0;
            *(float2*)(C + (size_t)(row + 8) * ldc + col) = v1;
        }
    }
#undef ISSUE
}

// ==================== BF16 tensor-core NT GEMM (2x rate, for attn @ V) ============
// CTA 128x128, 4 warps, warp tile 64x64, BK=64 bf16, 2-stage cp.async, 2 CTAs/SM.
// C[z] = A[z](M,K) * B[z](N,K)^T ; fp32 accum/out. z strides = element offsets.
#define BPITCH 36                       // u32 per smem row (72 bf16 = 144 B)
#define BSTG   (128 * BPITCH)           // u32 per operand stage
#define GEMM_BF_SMEM (4 * BSTG * 4)     // 73728 bytes

__global__ void __launch_bounds__(128, 2)
gemm_bf_k(const __nv_bfloat16* __restrict__ A, int lda, size_t sAz,
          const __nv_bfloat16* __restrict__ B, int ldb, size_t sBz,
          float* __restrict__ C, int ldc, size_t sCz,
          int K)
{
    extern __shared__ uint32_t smu[];
    const uint32_t smb = (uint32_t)__cvta_generic_to_shared(smu);
    const int tid  = threadIdx.x;
    const int wid  = tid >> 5, lane = tid & 31;
    const int wm   = wid & 1,  wn   = wid >> 1;
    const int gid  = lane >> 2, tig = lane & 3;
    const int m0   = blockIdx.y * 128, n0 = blockIdx.x * 128;

    A += (size_t)blockIdx.z * sAz;
    B += (size_t)blockIdx.z * sBz;
    C += (size_t)blockIdx.z * sCz;

    int lrow[8], lcc[8];
    #pragma unroll
    for (int i = 0; i < 8; i++) {
        int c = tid + i * 128;
        lrow[i] = c >> 3;       // 0..127
        lcc[i]  = c & 7;        // 16B chunk within 128B row
    }

    // one stage = A tile [128 x 64 bf16] + B tile; 8 chunks/thread/operand
#define BISSUE(s, kt)                                                                      \
    {                                                                                      \
        const int _k0 = (kt) << 6;                                                         \
        _Pragma("unroll")                                                                  \
        for (int i = 0; i < 8; i++) {                                                      \
            cp16(smb + (uint32_t)((((s) * BSTG) + lrow[i] * BPITCH) * 4 + lcc[i] * 16),    \
                 A + (size_t)(m0 + lrow[i]) * lda + _k0 + lcc[i] * 8);                     \
            cp16(smb + (uint32_t)((((2 + (s)) * BSTG) + lrow[i] * BPITCH) * 4 + lcc[i] * 16), \
                 B + (size_t)(n0 + lrow[i]) * ldb + _k0 + lcc[i] * 8);                     \
        }                                                                                  \
        asm volatile("cp.async.commit_group;");                                           \
    }

    float acc[4][8][4];
    #pragma unroll
    for (int mt = 0; mt < 4; mt++)
        #pragma unroll
        for (int nt = 0; nt < 8; nt++)
            #pragma unroll
            for (int q = 0; q < 4; q++) acc[mt][nt][q] = 0.0f;

    const int KT = K >> 6;
    BISSUE(0, 0);

    for (int kt = 0; kt < KT; kt++) {
        const int p = kt & 1;
        if (kt + 1 < KT) {
            BISSUE(p ^ 1, kt + 1);
            asm volatile("cp.async.wait_group 1;");
        } else {
            asm volatile("cp.async.wait_group 0;");
        }
        __syncthreads();

        #pragma unroll
        for (int ks = 0; ks < 4; ks++) {     // 4 x k16 per BK=64 stage
            uint32_t fa[4][4], fb[8][2];
            #pragma unroll
            for (int mt = 0; mt < 4; mt++) {
                const int mr = wm * 64 + mt * 16 + gid;
                const int base = p * BSTG + mr * BPITCH + ks * 8 + tig;
                fa[mt][0] = smu[base];
                fa[mt][1] = smu[base + 8 * BPITCH];
                fa[mt][2] = smu[base + 4];
                fa[mt][3] = smu[base + 8 * BPITCH + 4];
            }
            #pragma unroll
            for (int nt = 0; nt < 8; nt++) {
                const int nr = wn * 64 + nt * 8 + gid;
                const int bb = (2 + p) * BSTG + nr * BPITCH + ks * 8 + tig;
                fb[nt][0] = smu[bb];
                fb[nt][1] = smu[bb + 4];
            }
            #pragma unroll
            for (int nt = 0; nt < 8; nt++)
                #pragma unroll
                for (int mt = 0; mt < 4; mt++)
                    mma_bf16(acc[mt][nt], fa[mt], fb[nt][0], fb[nt][1]);
        }
        __syncthreads();
    }

    #pragma unroll
    for (int mt = 0; mt < 4; mt++) {
        const int row = m0 + wm * 64 + mt * 16 + gid;
        #pragma unroll
        for (int nt = 0; nt < 8; nt++) {
            const int col = n0 + wn * 64 + nt * 8 + tig * 2;
            *(float2*)(C + (size_t)row * ldc + col)       = make_float2(acc[mt][nt][0], acc[mt][nt][1]);
            *(float2*)(C + (size_t)(row + 8) * ldc + col) = make_float2(acc[mt][nt][2], acc[mt][nt][3]);
        }
    }
#undef BISSUE
}

// -------------------- transposes --------------------
__global__ void transpose_k(const float* __restrict__ src, int lds, size_t sSz,
                            float* __restrict__ dst, int ldd, size_t sDz)
{
    __shared__ float t[32][33];
    src += (size_t)blockIdx.z * sSz;
    dst += (size_t)blockIdx.z * sDz;
    int c0 = blockIdx.x * 32, r0 = blockIdx.y * 32;
    int tx = threadIdx.x, ty = threadIdx.y;
    #pragma unroll
    for (int j = 0; j < 32; j += 8)
        t[ty + j][tx] = src[(size_t)(r0 + ty + j) * lds + c0 + tx];
    __syncthreads();
    #pragma unroll
    for (int j = 0; j < 32; j += 8)
        dst[(size_t)(c0 + ty + j) * ldd + r0 + tx] = t[tx][ty + j];
}

// fp32 strided source -> bf16 transposed dest
__global__ void transpose_bf_k(const float* __restrict__ src, int lds, size_t sSz,
                               __nv_bfloat16* __restrict__ dst, int ldd, size_t sDz)
{
    __shared__ float t[32][33];
    src += (size_t)blockIdx.z * sSz;
    dst += (size_t)blockIdx.z * sDz;
    int c0 = blockIdx.x * 32, r0 = blockIdx.y * 32;
    int tx = threadIdx.x, ty = threadIdx.y;
    #pragma unroll
    for (int j = 0; j < 32; j += 8)
        t[ty + j][tx] = src[(size_t)(r0 + ty + j) * lds + c0 + tx];
    __syncthreads();
    #pragma unroll
    for (int j = 0; j < 32; j += 8)
        dst[(size_t)(c0 + ty + j) * ldd + r0 + tx] = __float2bfloat16_rn(t[tx][ty + j]);
}

// -------------------- LayerNorm (dim 64) --------------------
__global__ void ln_k(const float* __restrict__ x, const float* __restrict__ g,
                     const float* __restrict__ b, float* __restrict__ y, int rows)
{
    int w    = blockIdx.x * 8 + (threadIdx.x >> 5);
    int lane = threadIdx.x & 31;
    if (w >= rows) return;
    const float* xr = x + (size_t)w * 64;
    float v0 = xr[lane], v1 = xr[lane + 32];
    float s = v0 + v1;
    #pragma unroll
    for (int o = 16; o > 0; o >>= 1) s += __shfl_xor_sync(0xffffffffu, s, o);
    float m  = s * (1.0f / 64.0f);
    float d0 = v0 - m, d1 = v1 - m;
    float q  = d0 * d0 + d1 * d1;
    #pragma unroll
    for (int o = 16; o > 0; o >>= 1) q += __shfl_xor_sync(0xffffffffu, q, o);
    float inv = rsqrtf(q * (1.0f / 64.0f) + 1e-5f);
    float* yr = y + (size_t)w * 64;
    yr[lane]      = d0 * inv * g[lane]      + b[lane];
    yr[lane + 32] = d1 * inv * g[lane + 32] + b[lane + 32];
}

// ---- small fp32 GEMM (N=64 projections). Optional A2: A-tile = A + A2 (split-K fuse) ----
__global__ void __launch_bounds__(256)
gemm_k(const float* __restrict__ A, const float* __restrict__ A2, int lda, size_t sAz,
       const float* __restrict__ B, int ldb,
       float* __restrict__ C, int ldc, size_t sCz,
       int K,
       const float* __restrict__ bias,
       const float* __restrict__ resid, int ldr, size_t sRz,
       int do_gelu)
{
    __shared__ float As[16][68];
    __shared__ float Bs[16][68];
    int tx = threadIdx.x, ty = threadIdx.y;
    int t  = ty * 16 + tx;
    int m0 = blockIdx.y * 64, n0 = blockIdx.x * 64;

    A += (size_t)blockIdx.z * sAz;
    if (A2) A2 += (size_t)blockIdx.z * sAz;
    C += (size_t)blockIdx.z * sCz;
    if (resid) resid += (size_t)blockIdx.z * sRz;

    float acc[4][4] = {};
    int ar  = t / 4;
    int ac4 = (t % 4) * 4;
    int br  = t / 16;
    int bc4 = (t % 16) * 4;

    for (int k0 = 0; k0 < K; k0 += 16) {
        const size_t aoff = (size_t)(m0 + ar) * lda + k0 + ac4;
        if (A2) {
            #pragma unroll
            for (int q = 0; q < 4; q++) As[ac4 + q][ar] = A[aoff + q] + A2[aoff + q];
        } else {
            #pragma unroll
            for (int q = 0; q < 4; q++) As[ac4 + q][ar] = A[aoff + q];
        }
        const float* Bp = B + (size_t)(k0 + br) * ldb + n0 + bc4;
        #pragma unroll
        for (int q = 0; q < 4; q++) Bs[br][bc4 + q] = Bp[q];
        __syncthreads();
        #pragma unroll
        for (int kk = 0; kk < 16; kk++) {
            float a[4], b[4];
            #pragma unroll
            for (int i = 0; i < 4; i++) a[i] = As[kk][ty * 4 + i];
            #pragma unroll
            for (int j = 0; j < 4; j++) b[j] = Bs[kk][tx * 4 + j];
            #pragma unroll
            for (int i = 0; i < 4; i++)
                #pragma unroll
                for (int j = 0; j < 4; j++)
                    acc[i][j] = fmaf(a[i], b[j], acc[i][j]);
        }
        __syncthreads();
    }

    #pragma unroll
    for (int i = 0; i < 4; i++) {
        int row = m0 + ty * 4 + i;
        #pragma unroll
        for (int j = 0; j < 4; j++) {
            int col = n0 + tx * 4 + j;
            float v = acc[i][j];
            if (bias)    v += bias[col];
            if (do_gelu) v = 0.5f * v * (1.0f + erff(v * 0.70710678118654752f));
            if (resid)   v += resid[(size_t)row * ldr + col];
            C[(size_t)row * ldc + col] = v;
        }
    }
}

// -------------------- block reductions --------------------
__device__ __forceinline__ float blk_max(float v, float* wred, int wid, int lane) {
    #pragma unroll
    for (int o = 16; o > 0; o >>= 1) v = fmaxf(v, __shfl_xor_sync(0xffffffffu, v, o));
    if (lane == 0) wred[wid] = v;
    __syncthreads();
    float r = wred[0];
    #pragma unroll
    for (int i = 1; i < 8; i++) r = fmaxf(r, wred[i]);
    __syncthreads();
    return r;
}
__device__ __forceinline__ float blk_sum(float v, float* wred, int wid, int lane) {
    #pragma unroll
    for (int o = 16; o > 0; o >>= 1) v += __shfl_xor_sync(0xffffffffu, v, o);
    if (lane == 0) wred[wid] = v;
    __syncthreads();
    float r = 0.0f;
    #pragma unroll
    for (int i = 0; i < 8; i++) r += wred[i];
    __syncthreads();
    return r;
}

// ---- layer-0 masked softmax: reads fp32 A, writes bf16 attn AND the bitmask ----
__global__ void attn_softmax_k(const float* __restrict__ dots, const float* __restrict__ Am,
                               __nv_bfloat16* __restrict__ attnb, uint32_t* __restrict__ maskw)
{
    __shared__ float wred[8];
    __shared__ uint32_t mw[128];
    const int row = blockIdx.x, tid = threadIdx.x;
    const int wid = tid >> 5, lane = tid & 31;
    const float4* dr = (const float4*)(dots + (size_t)row * NTOK);
    const float4* ar = (const float4*)(Am   + (size_t)row * NTOK);
    const int dj = row >> 2, dl = row & 3;

    if (tid < 128) mw[tid] = 0u;
    __syncthreads();

    float4 r[4];
    float mx = -3.4e38f;
    #pragma unroll
    for (int i = 0; i < 4; i++) {
        int j = tid + i * 256;
        float4 d = dr[j], a = ar[j], v;
        uint32_t bits = 0;
        v.x = (a.x > 0.0f) ? (bits |= 1u, d.x) : -9e15f;
        v.y = (a.y > 0.0f) ? (bits |= 2u, d.y) : -9e15f;
        v.z = (a.z > 0.0f) ? (bits |= 4u, d.z) : -9e15f;
        v.w = (a.w > 0.0f) ? (bits |= 8u, d.w) : -9e15f;
        if (bits) atomicOr(&mw[j >> 3], bits << ((j & 7) * 4));
        if (j == dj) ((float*)&v)[dl] = 1.0f;
        r[i] = v;
        mx = fmaxf(fmaxf(fmaxf(mx, v.x), v.y), fmaxf(v.z, v.w));
    }
    mx = blk_max(mx, wred, wid, lane);

    float sum = 0.0f;
    #pragma unroll
    for (int i = 0; i < 4; i++) {
        r[i].x = __expf(r[i].x - mx); r[i].y = __expf(r[i].y - mx);
        r[i].z = __expf(r[i].z - mx); r[i].w = __expf(r[i].w - mx);
        sum += (r[i].x + r[i].y) + (r[i].z + r[i].w);
    }
    sum = blk_sum(sum, wred, wid, lane);
    float inv = 1.0f / sum;

    uint2* ob = (uint2*)(attnb + (size_t)row * NTOK);
    #pragma unroll
    for (int i = 0; i < 4; i++) {
        int j = tid + i * 256;
        uint2 u;
        u.x = pack_bf2(r[i].x * inv, r[i].y * inv);
        u.y = pack_bf2(r[i].z * inv, r[i].w * inv);
        ob[j] = u;
    }
    __syncthreads();
    if (tid < 128) maskw[row * 128 + tid] = mw[tid];
}

// ---- layer-1: masked softmax -> fp32 attn_out + bf16 attnb; plain softmax -> ds_out ----
__global__ void dual_softmax_k(const float* __restrict__ dots, const uint32_t* __restrict__ maskw,
                               float* __restrict__ attn_out, __nv_bfloat16* __restrict__ attnb,
                               float* __restrict__ ds_out)
{
    __shared__ float wred[8];
    const int row = blockIdx.x, tid = threadIdx.x;
    const int wid = tid >> 5, lane = tid & 31;
    const float4* dr = (const float4*)(dots + (size_t)row * NTOK);
    const uint32_t* mrow = maskw + row * 128;
    const int dj = row >> 2, dl = row & 3;

    float4 rv[4], mv[4];
    float mxr = -3.4e38f, mxm = -3.4e38f;
    #pragma unroll
    for (int i = 0; i < 4; i++) {
        int j = tid + i * 256;
        float4 d = dr[j], v;
        uint32_t bits = mrow[j >> 3] >> ((j & 7) * 4);
        v.x = (bits & 1u) ? d.x : -9e15f;
        v.y = (bits & 2u) ? d.y : -9e15f;
        v.z = (bits & 4u) ? d.z : -9e15f;
        v.w = (bits & 8u) ? d.w : -9e15f;
        if (j == dj) ((float*)&v)[dl] = 1.0f;
        rv[i] = d; mv[i] = v;
        mxr = fmaxf(fmaxf(fmaxf(mxr, d.x), d.y), fmaxf(d.z, d.w));
        mxm = fmaxf(fmaxf(fmaxf(mxm, v.x), v.y), fmaxf(v.z, v.w));
    }
    mxm = blk_max(mxm, wred, wid, lane);
    mxr = blk_max(mxr, wred, wid, lane);

    float sm = 0.0f, sr = 0.0f;
    #pragma unroll
    for (int i = 0; i < 4; i++) {
        mv[i].x = __expf(mv[i].x - mxm); mv[i].y = __expf(mv[i].y - mxm);
        mv[i].z = __expf(mv[i].z - mxm); mv[i].w = __expf(mv[i].w - mxm);
        rv[i].x = __expf(rv[i].x - mxr); rv[i].y = __expf(rv[i].y - mxr);
        rv[i].z = __expf(rv[i].z - mxr); rv[i].w = __expf(rv[i].w - mxr);
        sm += (mv[i].x + mv[i].y) + (mv[i].z + mv[i].w);
        sr += (rv[i].x + rv[i].y) + (rv[i].z + rv[i].w);
    }
    sm = blk_sum(sm, wred, wid, lane);
    sr = blk_sum(sr, wred, wid, lane);
    float invm = 1.0f / sm, invr = 1.0f / sr;

    float4* o2 = (float4*)(attn_out + (size_t)row * NTOK);
    uint2*  ob = (uint2*)(attnb + (size_t)row * NTOK);
    float4* o3 = (float4*)(ds_out   + (size_t)row * NTOK);
    #pragma unroll
    for (int i = 0; i < 4; i++) {
        int j = tid + i * 256;
        float4 vo = make_float4(mv[i].x * invm, mv[i].y * invm, mv[i].z * invm, mv[i].w * invm);
        o2[j] = vo;
        uint2 u;
        u.x = pack_bf2(vo.x, vo.y);
        u.y = pack_bf2(vo.z, vo.w);
        ob[j] = u;
        o3[j] = make_float4(rv[i].x * invr, rv[i].y * invr, rv[i].z * invr, rv[i].w * invr);
    }
}

// -------------------- host orchestration --------------------
extern "C" void kernel_launch(void* const* d_in, const int* in_sizes, int n_in,
                              void* d_out, int out_size)
{
    const float* embed = (const float*)d_in[0];
    const float* Am    = (const float*)d_in[1];
    const float* g1    = (const float*)d_in[2];
    const float* b1    = (const float*)d_in[3];
    const float* Wqkv  = (const float*)d_in[4];
    const float* Wout  = (const float*)d_in[5];
    const float* bout  = (const float*)d_in[6];
    const float* g2    = (const float*)d_in[7];
    const float* b2    = (const float*)d_in[8];
    const float* W1    = (const float*)d_in[9];
    const float* bb1   = (const float*)d_in[10];
    const float* W2    = (const float*)d_in[11];
    const float* bb2   = (const float*)d_in[12];
    const float* gf    = (const float*)d_in[13];
    const float* bf    = (const float*)d_in[14];

    float *xg, *xng, *qkvg, *dotsg, *wTg;
    __nv_bfloat16 *attnbg, *vTbg;
    uint32_t* maskg;
    cudaGetSymbolAddress((void**)&xg,     g_x);
    cudaGetSymbolAddress((void**)&xng,    g_xn);
    cudaGetSymbolAddress((void**)&qkvg,   g_qkv);
    cudaGetSymbolAddress((void**)&dotsg,  g_dots);
    cudaGetSymbolAddress((void**)&attnbg, g_attnb);
    cudaGetSymbolAddress((void**)&vTbg,   g_vTb);
    cudaGetSymbolAddress((void**)&wTg,    g_wT);
    cudaGetSymbolAddress((void**)&maskg,  g_mask);

    cudaFuncSetAttribute(gemm_tc_k, cudaFuncAttributeMaxDynamicSharedMemorySize, GEMM_TC_SMEM);
    cudaFuncSetAttribute(gemm_bf_k, cudaFuncAttributeMaxDynamicSharedMemorySize, GEMM_BF_SMEM);

    float* out_x    = (float*)d_out;
    float* out_attn = out_x + (size_t)ROWS * DIM64;
    float* out_ds   = out_attn + (size_t)NTOK * NTOK;

    dim3 blk(16, 16);
    dim3 tblk(32, 8);
    const size_t avHalf = (size_t)NTOK * 512;   // split-K partial stride (in g_dots)

    for (int l = 0; l < 2; l++) {
        const float* src = l ? xg : embed;
        // xn = LN(x)
        ln_k<<<ROWS / 8, 256>>>(src, g1 + l * 64, b1 + l * 64, xng, ROWS);
        // wT = Wqkv[l]^T
        transpose_k<<<dim3(768 / 32, 64 / 32, 1), tblk>>>(
            Wqkv + (size_t)l * 64 * 768, 768, 0, wTg, 64, 0);
        // qkv = xn @ Wqkv[l] (NT): [8192,64] x [768,64]^T
        gemm_tc_k<<<dim3(768 / 128, ROWS / 128, 1), 128, GEMM_TC_SMEM>>>(
            xng, 64, 0, wTg, 64, 0, qkvg, 768, 0, 64, 1.0f);
        // dots = 0.125 * q0 @ k0^T (batch 0 only)
        gemm_tc_k<<<dim3(NTOK / 128, NTOK / 128, 1), 128, GEMM_TC_SMEM>>>(
            qkvg, 768, 0, qkvg + 256, 768, 0, dotsg, NTOK, 0, 256, 0.125f);
        // softmax -> bf16 attn (+ fp32/ds outputs on last layer)
        if (l == 0)
            attn_softmax_k<<<NTOK, 256>>>(dotsg, Am, attnbg, maskg);
        else
            dual_softmax_k<<<NTOK, 256>>>(dotsg, maskg, out_attn, attnbg, out_ds);
        // vT bf16 (both batches -> [512][4096])
        transpose_bf_k<<<dim3(INNERD / 32, NTOK / 32, BATCH), tblk>>>(
            qkvg + 512, 768, (size_t)NTOK * 768,
            vTbg, NTOK, (size_t)INNERD * NTOK);
        // av = attn @ vT^T in bf16, split-K x2 (fp32 partials into free dots scratch)
        gemm_bf_k<<<dim3(512 / 128, NTOK / 128, 2), 128, GEMM_BF_SMEM>>>(
            attnbg, NTOK, 2048, vTbg, NTOK, 2048, dotsg, 512, avHalf, 2048);
        // x[z] = xn[z] + ((p0+p1)[:, z*256..] @ Wout[l] + bout[l]) — split-K add fused
        gemm_k<<<dim3(1, NTOK / 64, 2), blk>>>(
            dotsg, dotsg + avHalf, 512, (size_t)INNERD,
            Wout + (size_t)l * INNERD * 64, 64,
            xg, 64, (size_t)NTOK * 64, INNERD,
            bout + l * 64, xng, 64, (size_t)NTOK * 64, 0);
        // xm = LN(x)
        ln_k<<<ROWS / 8, 256>>>(xg, g2 + l * 64, b2 + l * 64, xng, ROWS);
        // h = gelu(xm @ W1 + bb1)
        gemm_k<<<dim3(1, ROWS / 64, 1), blk>>>(
            xng, nullptr, 64, 0, W1 + (size_t)l * 64 * 64, 64, qkvg, 64, 0, 64,
            bb1 + l * 64, nullptr, 64, 0, 1);
        // x = xm + (h @ W2 + bb2)
        gemm_k<<<dim3(1, ROWS / 64, 1), blk>>>(
            qkvg, nullptr, 64, 0, W2 + (size_t)l * 64 * 64, 64, xg, 64, 0, 64,
            bb2 + l * 64, xng, 64, 0, 0);
    }
    // final LN -> output
    ln_k<<<ROWS / 8, 256>>>(xg, gf, bf, out_x, ROWS);
}

// round 15
// speedup vs baseline: 2.0482x; 1.1245x over previous
#include <cuda_runtime.h>
#include <cuda_bf16.h>
#include <math.h>
#include <stdint.h>

#define NTOK   4096
#define BATCH  2
#define DIM64  64
#define INNERD 256
#define ROWS   (BATCH * NTOK)   // 8192

// -------------------- device scratch --------------------
__device__ float g_xn  [ROWS * DIM64];
__device__ float g_x   [ROWS * DIM64];
__device__ float g_qkv [ROWS * INNERD * 3];
__device__ float g_dots[(size_t)NTOK * NTOK];           // reused as split-K partials after softmax
__device__ __nv_bfloat16 g_attnb[(size_t)NTOK * NTOK];  // bf16 attn for the AV GEMM
__device__ __nv_bfloat16 g_vTb [BATCH * INNERD * NTOK]; // bf16 [512][4096]
__device__ __nv_bfloat16 g_qb  [NTOK * INNERD];         // bf16 q (x0.125), batch 0
__device__ __nv_bfloat16 g_kb  [NTOK * INNERD];         // bf16 k, batch 0
__device__ float g_wT  [768 * 64];
__device__ uint32_t g_mask[NTOK * 128];                 // adjacency bitmask, built in layer 0

// -------------------- helpers --------------------
__device__ __forceinline__ void mma_tf32(float c[4], const float a[4], const float b[2]) {
    asm volatile(
        "mma.sync.aligned.m16n8k8.row.col.f32.tf32.tf32.f32 "
        "{%0,%1,%2,%3}, {%4,%5,%6,%7}, {%8,%9}, {%0,%1,%2,%3};"
        : "+f"(c[0]), "+f"(c[1]), "+f"(c[2]), "+f"(c[3])
        : "r"(__float_as_uint(a[0])), "r"(__float_as_uint(a[1])),
          "r"(__float_as_uint(a[2])), "r"(__float_as_uint(a[3])),
          "r"(__float_as_uint(b[0])), "r"(__float_as_uint(b[1])));
}

__device__ __forceinline__ void mma_bf16(float c[4], const uint32_t a[4],
                                         uint32_t b0, uint32_t b1) {
    asm volatile(
        "mma.sync.aligned.m16n8k16.row.col.f32.bf16.bf16.f32 "
        "{%0,%1,%2,%3}, {%4,%5,%6,%7}, {%8,%9}, {%0,%1,%2,%3};"
        : "+f"(c[0]), "+f"(c[1]), "+f"(c[2]), "+f"(c[3])
        : "r"(a[0]), "r"(a[1]), "r"(a[2]), "r"(a[3]), "r"(b0), "r"(b1));
}

__device__ __forceinline__ void cp16(uint32_t dst, const void* src) {
    asm volatile("cp.async.cg.shared.global [%0], [%1], 16;" :: "r"(dst), "l"(src));
}

__device__ __forceinline__ uint32_t pack_bf2(float a, float b) {
    __nv_bfloat162 h = __floats2bfloat162_rn(a, b);
    return *(uint32_t*)&h;
}

// ==================== TF32 tensor-core NT GEMM (qkv projection only) ============
#define SPITCH 36
#define ASTG   (128 * SPITCH)
#define AS(p, m, k) sm[(p) * ASTG + (m) * SPITCH + (k)]
#define BS(p, n, k) sm[(2 + (p)) * ASTG + (n) * SPITCH + (k)]
#define GEMM_TC_SMEM (4 * ASTG * (int)sizeof(float))   // 73728 bytes

__global__ void __launch_bounds__(128, 2)
gemm_tc_k(const float* __restrict__ A, int lda, size_t sAz,
          const float* __restrict__ B, int ldb, size_t sBz,
          float* __restrict__ C, int ldc, size_t sCz,
          int K, float alpha)
{
    extern __shared__ float sm[];
    const uint32_t smb = (uint32_t)__cvta_generic_to_shared(sm);
    const int tid  = threadIdx.x;
    const int wid  = tid >> 5, lane = tid & 31;
    const int wm   = wid & 1,  wn   = wid >> 1;
    const int gid  = lane >> 2, tig = lane & 3;
    const int m0   = blockIdx.y * 128, n0 = blockIdx.x * 128;

    A += (size_t)blockIdx.z * sAz;
    B += (size_t)blockIdx.z * sBz;
    C += (size_t)blockIdx.z * sCz;

    int lrow[8], lkq[8];
    #pragma unroll
    for (int i = 0; i < 8; i++) {
        int c = tid + i * 128;
        lrow[i] = c >> 3;
        lkq[i]  = (c & 7) << 2;
    }

#define ISSUE(s, kt)                                                                     \
    {                                                                                    \
        const int _k0 = (kt) << 5;                                                       \
        _Pragma("unroll")                                                                \
        for (int i = 0; i < 8; i++) {                                                    \
            cp16(smb + (uint32_t)((((s) * ASTG) + lrow[i] * SPITCH + lkq[i]) * 4),       \
                 A + (size_t)(m0 + lrow[i]) * lda + _k0 + lkq[i]);                       \
            cp16(smb + (uint32_t)((((2 + (s)) * ASTG) + lrow[i] * SPITCH + lkq[i]) * 4), \
                 B + (size_t)(n0 + lrow[i]) * ldb + _k0 + lkq[i]);                       \
        }                                                                                \
        asm volatile("cp.async.commit_group;");                                         \
    }

    float acc[4][8][4];
    #pragma unroll
    for (int mt = 0; mt < 4; mt++)
        #pragma unroll
        for (int nt = 0; nt < 8; nt++)
            #pragma unroll
            for (int q = 0; q < 4; q++) acc[mt][nt][q] = 0.0f;

    const int KT = K >> 5;
    ISSUE(0, 0);

    for (int kt = 0; kt < KT; kt++) {
        const int p = kt & 1;
        if (kt + 1 < KT) {
            ISSUE(p ^ 1, kt + 1);
            asm volatile("cp.async.wait_group 1;");
        } else {
            asm volatile("cp.async.wait_group 0;");
        }
        __syncthreads();

        #pragma unroll
        for (int ks = 0; ks < 4; ks++) {
            const int kb = ks << 3;
            float fa[4][4];
            float fb[8][2];
            #pragma unroll
            for (int mt = 0; mt < 4; mt++) {
                const int mr = wm * 64 + mt * 16 + gid;
                fa[mt][0] = AS(p, mr,     kb + tig);
                fa[mt][1] = AS(p, mr + 8, kb + tig);
                fa[mt][2] = AS(p, mr,     kb + tig + 4);
                fa[mt][3] = AS(p, mr + 8, kb + tig + 4);
            }
            #pragma unroll
            for (int nt = 0; nt < 8; nt++) {
                const int nr = wn * 64 + nt * 8 + gid;
                fb[nt][0] = BS(p, nr, kb + tig);
                fb[nt][1] = BS(p, nr, kb + tig + 4);
            }
            #pragma unroll
            for (int nt = 0; nt < 8; nt++)
                #pragma unroll
                for (int mt = 0; mt < 4; mt++)
                    mma_tf32(acc[mt][nt], fa[mt], fb[nt]);
        }
        __syncthreads();
    }

    #pragma unroll
    for (int mt = 0; mt < 4; mt++) {
        const int row = m0 + wm * 64 + mt * 16 + gid;
        #pragma unroll
        for (int nt = 0; nt < 8; nt++) {
            const int col = n0 + wn * 64 + nt * 8 + tig * 2;
            float2 v0 = make_float2(acc[mt][nt][0] * alpha, acc[mt][nt][1] * alpha);
            float2 v1 = make_float2(acc[mt][nt][2] * alpha, acc[mt][nt][3] * alpha);
            *(float2*)(C + (size_t)row * ldc + col)       = v0;
            *(float2*)(C + (size_t)(row + 8) * ldc + col) = v1;
        }
    }
#undef ISSUE
}

// ==================== BF16 tensor-core NT GEMM (QK^T and attn @ V) ============
// CTA 128x128, 4 warps, warp tile 64x64, BK=64 bf16, 2-stage cp.async, 2 CTAs/SM.
#define BPITCH 36
#define BSTG   (128 * BPITCH)
#define GEMM_BF_SMEM (4 * BSTG * 4)     // 73728 bytes

__global__ void __launch_bounds__(128, 2)
gemm_bf_k(const __nv_bfloat16* __restrict__ A, int lda, size_t sAz,
          const __nv_bfloat16* __restrict__ B, int ldb, size_t sBz,
          float* __restrict__ C, int ldc, size_t sCz,
          int K)
{
    extern __shared__ uint32_t smu[];
    const uint32_t smb = (uint32_t)__cvta_generic_to_shared(smu);
    const int tid  = threadIdx.x;
    const int wid  = tid >> 5, lane = tid & 31;
    const int wm   = wid & 1,  wn   = wid >> 1;
    const int gid  = lane >> 2, tig = lane & 3;
    const int m0   = blockIdx.y * 128, n0 = blockIdx.x * 128;

    A += (size_t)blockIdx.z * sAz;
    B += (size_t)blockIdx.z * sBz;
    C += (size_t)blockIdx.z * sCz;

    int lrow[8], lcc[8];
    #pragma unroll
    for (int i = 0; i < 8; i++) {
        int c = tid + i * 128;
        lrow[i] = c >> 3;
        lcc[i]  = c & 7;
    }

#define BISSUE(s, kt)                                                                      \
    {                                                                                      \
        const int _k0 = (kt) << 6;                                                         \
        _Pragma("unroll")                                                                  \
        for (int i = 0; i < 8; i++) {                                                      \
            cp16(smb + (uint32_t)((((s) * BSTG) + lrow[i] * BPITCH) * 4 + lcc[i] * 16),    \
                 A + (size_t)(m0 + lrow[i]) * lda + _k0 + lcc[i] * 8);                     \
            cp16(smb + (uint32_t)((((2 + (s)) * BSTG) + lrow[i] * BPITCH) * 4 + lcc[i] * 16), \
                 B + (size_t)(n0 + lrow[i]) * ldb + _k0 + lcc[i] * 8);                     \
        }                                                                                  \
        asm volatile("cp.async.commit_group;");                                           \
    }

    float acc[4][8][4];
    #pragma unroll
    for (int mt = 0; mt < 4; mt++)
        #pragma unroll
        for (int nt = 0; nt < 8; nt++)
            #pragma unroll
            for (int q = 0; q < 4; q++) acc[mt][nt][q] = 0.0f;

    const int KT = K >> 6;
    BISSUE(0, 0);

    for (int kt = 0; kt < KT; kt++) {
        const int p = kt & 1;
        if (kt + 1 < KT) {
            BISSUE(p ^ 1, kt + 1);
            asm volatile("cp.async.wait_group 1;");
        } else {
            asm volatile("cp.async.wait_group 0;");
        }
        __syncthreads();

        #pragma unroll
        for (int ks = 0; ks < 4; ks++) {
            uint32_t fa[4][4], fb[8][2];
            #pragma unroll
            for (int mt = 0; mt < 4; mt++) {
                const int mr = wm * 64 + mt * 16 + gid;
                const int base = p * BSTG + mr * BPITCH + ks * 8 + tig;
                fa[mt][0] = smu[base];
                fa[mt][1] = smu[base + 8 * BPITCH];
                fa[mt][2] = smu[base + 4];
                fa[mt][3] = smu[base + 8 * BPITCH + 4];
            }
            #pragma unroll
            for (int nt = 0; nt < 8; nt++) {
                const int nr = wn * 64 + nt * 8 + gid;
                const int bb = (2 + p) * BSTG + nr * BPITCH + ks * 8 + tig;
                fb[nt][0] = smu[bb];
                fb[nt][1] = smu[bb + 4];
            }
            #pragma unroll
            for (int nt = 0; nt < 8; nt++)
                #pragma unroll
                for (int mt = 0; mt < 4; mt++)
                    mma_bf16(acc[mt][nt], fa[mt], fb[nt][0], fb[nt][1]);
        }
        __syncthreads();
    }

    #pragma unroll
    for (int mt = 0; mt < 4; mt++) {
        const int row = m0 + wm * 64 + mt * 16 + gid;
        #pragma unroll
        for (int nt = 0; nt < 8; nt++) {
            const int col = n0 + wn * 64 + nt * 8 + tig * 2;
            *(float2*)(C + (size_t)row * ldc + col)       = make_float2(acc[mt][nt][0], acc[mt][nt][1]);
            *(float2*)(C + (size_t)(row + 8) * ldc + col) = make_float2(acc[mt][nt][2], acc[mt][nt][3]);
        }
    }
#undef BISSUE
}

// ---- peel q (x0.125) and k from fp32 qkv into contiguous bf16 [4096,256] ----
__global__ void qk_to_bf_k(const float* __restrict__ qkv,
                           __nv_bfloat16* __restrict__ qb, __nv_bfloat16* __restrict__ kb)
{
    int i = blockIdx.x * 256 + threadIdx.x;        // 0 .. 4096*64-1  (float4 units)
    int row = i >> 6, c4 = (i & 63) << 2;
    const float4 q4 = *(const float4*)(qkv + (size_t)row * 768 + c4);
    const float4 k4 = *(const float4*)(qkv + (size_t)row * 768 + 256 + c4);
    uint2 uq, uk;
    uq.x = pack_bf2(q4.x * 0.125f, q4.y * 0.125f);
    uq.y = pack_bf2(q4.z * 0.125f, q4.w * 0.125f);
    uk.x = pack_bf2(k4.x, k4.y);
    uk.y = pack_bf2(k4.z, k4.w);
    *(uint2*)(qb + (size_t)row * 256 + c4) = uq;
    *(uint2*)(kb + (size_t)row * 256 + c4) = uk;
}

// -------------------- transposes --------------------
__global__ void transpose_k(const float* __restrict__ src, int lds, size_t sSz,
                            float* __restrict__ dst, int ldd, size_t sDz)
{
    __shared__ float t[32][33];
    src += (size_t)blockIdx.z * sSz;
    dst += (size_t)blockIdx.z * sDz;
    int c0 = blockIdx.x * 32, r0 = blockIdx.y * 32;
    int tx = threadIdx.x, ty = threadIdx.y;
    #pragma unroll
    for (int j = 0; j < 32; j += 8)
        t[ty + j][tx] = src[(size_t)(r0 + ty + j) * lds + c0 + tx];
    __syncthreads();
    #pragma unroll
    for (int j = 0; j < 32; j += 8)
        dst[(size_t)(c0 + ty + j) * ldd + r0 + tx] = t[tx][ty + j];
}

__global__ void transpose_bf_k(const float* __restrict__ src, int lds, size_t sSz,
                               __nv_bfloat16* __restrict__ dst, int ldd, size_t sDz)
{
    __shared__ float t[32][33];
    src += (size_t)blockIdx.z * sSz;
    dst += (size_t)blockIdx.z * sDz;
    int c0 = blockIdx.x * 32, r0 = blockIdx.y * 32;
    int tx = threadIdx.x, ty = threadIdx.y;
    #pragma unroll
    for (int j = 0; j < 32; j += 8)
        t[ty + j][tx] = src[(size_t)(r0 + ty + j) * lds + c0 + tx];
    __syncthreads();
    #pragma unroll
    for (int j = 0; j < 32; j += 8)
        dst[(size_t)(c0 + ty + j) * ldd + r0 + tx] = __float2bfloat16_rn(t[tx][ty + j]);
}

// -------------------- LayerNorm (dim 64) --------------------
__global__ void ln_k(const float* __restrict__ x, const float* __restrict__ g,
                     const float* __restrict__ b, float* __restrict__ y, int rows)
{
    int w    = blockIdx.x * 8 + (threadIdx.x >> 5);
    int lane = threadIdx.x & 31;
    if (w >= rows) return;
    const float* xr = x + (size_t)w * 64;
    float v0 = xr[lane], v1 = xr[lane + 32];
    float s = v0 + v1;
    #pragma unroll
    for (int o = 16; o > 0; o >>= 1) s += __shfl_xor_sync(0xffffffffu, s, o);
    float m  = s * (1.0f / 64.0f);
    float d0 = v0 - m, d1 = v1 - m;
    float q  = d0 * d0 + d1 * d1;
    #pragma unroll
    for (int o = 16; o > 0; o >>= 1) q += __shfl_xor_sync(0xffffffffu, q, o);
    float inv = rsqrtf(q * (1.0f / 64.0f) + 1e-5f);
    float* yr = y + (size_t)w * 64;
    yr[lane]      = d0 * inv * g[lane]      + b[lane];
    yr[lane + 32] = d1 * inv * g[lane + 32] + b[lane + 32];
}

// ---- small fp32 GEMM (N=64 projections). Optional A2: A-tile = A + A2 (split-K fuse) ----
__global__ void __launch_bounds__(256)
gemm_k(const float* __restrict__ A, const float* __restrict__ A2, int lda, size_t sAz,
       const float* __restrict__ B, int ldb,
       float* __restrict__ C, int ldc, size_t sCz,
       int K,
       const float* __restrict__ bias,
       const float* __restrict__ resid, int ldr, size_t sRz,
       int do_gelu)
{
    __shared__ float As[16][68];
    __shared__ float Bs[16][68];
    int tx = threadIdx.x, ty = threadIdx.y;
    int t  = ty * 16 + tx;
    int m0 = blockIdx.y * 64, n0 = blockIdx.x * 64;

    A += (size_t)blockIdx.z * sAz;
    if (A2) A2 += (size_t)blockIdx.z * sAz;
    C += (size_t)blockIdx.z * sCz;
    if (resid) resid += (size_t)blockIdx.z * sRz;

    float acc[4][4] = {};
    int ar  = t / 4;
    int ac4 = (t % 4) * 4;
    int br  = t / 16;
    int bc4 = (t % 16) * 4;

    for (int k0 = 0; k0 < K; k0 += 16) {
        const size_t aoff = (size_t)(m0 + ar) * lda + k0 + ac4;
        if (A2) {
            #pragma unroll
            for (int q = 0; q < 4; q++) As[ac4 + q][ar] = A[aoff + q] + A2[aoff + q];
        } else {
            #pragma unroll
            for (int q = 0; q < 4; q++) As[ac4 + q][ar] = A[aoff + q];
        }
        const float* Bp = B + (size_t)(k0 + br) * ldb + n0 + bc4;
        #pragma unroll
        for (int q = 0; q < 4; q++) Bs[br][bc4 + q] = Bp[q];
        __syncthreads();
        #pragma unroll
        for (int kk = 0; kk < 16; kk++) {
            float a[4], b[4];
            #pragma unroll
            for (int i = 0; i < 4; i++) a[i] = As[kk][ty * 4 + i];
            #pragma unroll
            for (int j = 0; j < 4; j++) b[j] = Bs[kk][tx * 4 + j];
            #pragma unroll
            for (int i = 0; i < 4; i++)
                #pragma unroll
                for (int j = 0; j < 4; j++)
                    acc[i][j] = fmaf(a[i], b[j], acc[i][j]);
        }
        __syncthreads();
    }

    #pragma unroll
    for (int i = 0; i < 4; i++) {
        int row = m0 + ty * 4 + i;
        #pragma unroll
        for (int j = 0; j < 4; j++) {
            int col = n0 + tx * 4 + j;
            float v = acc[i][j];
            if (bias)    v += bias[col];
            if (do_gelu) v = 0.5f * v * (1.0f + erff(v * 0.70710678118654752f));
            if (resid)   v += resid[(size_t)row * ldr + col];
            C[(size_t)row * ldc + col] = v;
        }
    }
}

// -------------------- block reductions --------------------
__device__ __forceinline__ float blk_max(float v, float* wred, int wid, int lane) {
    #pragma unroll
    for (int o = 16; o > 0; o >>= 1) v = fmaxf(v, __shfl_xor_sync(0xffffffffu, v, o));
    if (lane == 0) wred[wid] = v;
    __syncthreads();
    float r = wred[0];
    #pragma unroll
    for (int i = 1; i < 8; i++) r = fmaxf(r, wred[i]);
    __syncthreads();
    return r;
}
__device__ __forceinline__ float blk_sum(float v, float* wred, int wid, int lane) {
    #pragma unroll
    for (int o = 16; o > 0; o >>= 1) v += __shfl_xor_sync(0xffffffffu, v, o);
    if (lane == 0) wred[wid] = v;
    __syncthreads();
    float r = 0.0f;
    #pragma unroll
    for (int i = 0; i < 8; i++) r += wred[i];
    __syncthreads();
    return r;
}

// ---- layer-0 masked softmax: reads fp32 A, writes bf16 attn AND the bitmask ----
__global__ void attn_softmax_k(const float* __restrict__ dots, const float* __restrict__ Am,
                               __nv_bfloat16* __restrict__ attnb, uint32_t* __restrict__ maskw)
{
    __shared__ float wred[8];
    __shared__ uint32_t mw[128];
    const int row = blockIdx.x, tid = threadIdx.x;
    const int wid = tid >> 5, lane = tid & 31;
    const float4* dr = (const float4*)(dots + (size_t)row * NTOK);
    const float4* ar = (const float4*)(Am   + (size_t)row * NTOK);
    const int dj = row >> 2, dl = row & 3;

    if (tid < 128) mw[tid] = 0u;
    __syncthreads();

    float4 r[4];
    float mx = -3.4e38f;
    #pragma unroll
    for (int i = 0; i < 4; i++) {
        int j = tid + i * 256;
        float4 d = dr[j], a = ar[j], v;
        uint32_t bits = 0;
        v.x = (a.x > 0.0f) ? (bits |= 1u, d.x) : -9e15f;
        v.y = (a.y > 0.0f) ? (bits |= 2u, d.y) : -9e15f;
        v.z = (a.z > 0.0f) ? (bits |= 4u, d.z) : -9e15f;
        v.w = (a.w > 0.0f) ? (bits |= 8u, d.w) : -9e15f;
        if (bits) atomicOr(&mw[j >> 3], bits << ((j & 7) * 4));
        if (j == dj) ((float*)&v)[dl] = 1.0f;
        r[i] = v;
        mx = fmaxf(fmaxf(fmaxf(mx, v.x), v.y), fmaxf(v.z, v.w));
    }
    mx = blk_max(mx, wred, wid, lane);

    float sum = 0.0f;
    #pragma unroll
    for (int i = 0; i < 4; i++) {
        r[i].x = __expf(r[i].x - mx); r[i].y = __expf(r[i].y - mx);
        r[i].z = __expf(r[i].z - mx); r[i].w = __expf(r[i].w - mx);
        sum += (r[i].x + r[i].y) + (r[i].z + r[i].w);
    }
    sum = blk_sum(sum, wred, wid, lane);
    float inv = 1.0f / sum;

    uint2* ob = (uint2*)(attnb + (size_t)row * NTOK);
    #pragma unroll
    for (int i = 0; i < 4; i++) {
        int j = tid + i * 256;
        uint2 u;
        u.x = pack_bf2(r[i].x * inv, r[i].y * inv);
        u.y = pack_bf2(r[i].z * inv, r[i].w * inv);
        ob[j] = u;
    }
    __syncthreads();
    if (tid < 128) maskw[row * 128 + tid] = mw[tid];
}

// ---- layer-1: masked softmax -> fp32 attn_out + bf16 attnb; plain softmax -> ds_out ----
__global__ void dual_softmax_k(const float* __restrict__ dots, const uint32_t* __restrict__ maskw,
                               float* __restrict__ attn_out, __nv_bfloat16* __restrict__ attnb,
                               float* __restrict__ ds_out)
{
    __shared__ float wred[8];
    const int row = blockIdx.x, tid = threadIdx.x;
    const int wid = tid >> 5, lane = tid & 31;
    const float4* dr = (const float4*)(dots + (size_t)row * NTOK);
    const uint32_t* mrow = maskw + row * 128;
    const int dj = row >> 2, dl = row & 3;

    float4 rv[4], mv[4];
    float mxr = -3.4e38f, mxm = -3.4e38f;
    #pragma unroll
    for (int i = 0; i < 4; i++) {
        int j = tid + i * 256;
        float4 d = dr[j], v;
        uint32_t bits = mrow[j >> 3] >> ((j & 7) * 4);
        v.x = (bits & 1u) ? d.x : -9e15f;
        v.y = (bits & 2u) ? d.y : -9e15f;
        v.z = (bits & 4u) ? d.z : -9e15f;
        v.w = (bits & 8u) ? d.w : -9e15f;
        if (j == dj) ((float*)&v)[dl] = 1.0f;
        rv[i] = d; mv[i] = v;
        mxr = fmaxf(fmaxf(fmaxf(mxr, d.x), d.y), fmaxf(d.z, d.w));
        mxm = fmaxf(fmaxf(fmaxf(mxm, v.x), v.y), fmaxf(v.z, v.w));
    }
    mxm = blk_max(mxm, wred, wid, lane);
    mxr = blk_max(mxr, wred, wid, lane);

    float sm = 0.0f, sr = 0.0f;
    #pragma unroll
    for (int i = 0; i < 4; i++) {
        mv[i].x = __expf(mv[i].x - mxm); mv[i].y = __expf(mv[i].y - mxm);
        mv[i].z = __expf(mv[i].z - mxm); mv[i].w = __expf(mv[i].w - mxm);
        rv[i].x = __expf(rv[i].x - mxr); rv[i].y = __expf(rv[i].y - mxr);
        rv[i].z = __expf(rv[i].z - mxr); rv[i].w = __expf(rv[i].w - mxr);
        sm += (mv[i].x + mv[i].y) + (mv[i].z + mv[i].w);
        sr += (rv[i].x + rv[i].y) + (rv[i].z + rv[i].w);
    }
    sm = blk_sum(sm, wred, wid, lane);
    sr = blk_sum(sr, wred, wid, lane);
    float invm = 1.0f / sm, invr = 1.0f / sr;

    float4* o2 = (float4*)(attn_out + (size_t)row * NTOK);
    uint2*  ob = (uint2*)(attnb + (size_t)row * NTOK);
    float4* o3 = (float4*)(ds_out   + (size_t)row * NTOK);
    #pragma unroll
    for (int i = 0; i < 4; i++) {
        int j = tid + i * 256;
        float4 vo = make_float4(mv[i].x * invm, mv[i].y * invm, mv[i].z * invm, mv[i].w * invm);
        o2[j] = vo;
        uint2 u;
        u.x = pack_bf2(vo.x, vo.y);
        u.y = pack_bf2(vo.z, vo.w);
        ob[j] = u;
        o3[j] = make_float4(rv[i].x * invr, rv[i].y * invr, rv[i].z * invr, rv[i].w * invr);
    }
}

// -------------------- host orchestration --------------------
extern "C" void kernel_launch(void* const* d_in, const int* in_sizes, int n_in,
                              void* d_out, int out_size)
{
    const float* embed = (const float*)d_in[0];
    const float* Am    = (const float*)d_in[1];
    const float* g1    = (const float*)d_in[2];
    const float* b1    = (const float*)d_in[3];
    const float* Wqkv  = (const float*)d_in[4];
    const float* Wout  = (const float*)d_in[5];
    const float* bout  = (const float*)d_in[6];
    const float* g2    = (const float*)d_in[7];
    const float* b2    = (const float*)d_in[8];
    const float* W1    = (const float*)d_in[9];
    const float* bb1   = (const float*)d_in[10];
    const float* W2    = (const float*)d_in[11];
    const float* bb2   = (const float*)d_in[12];
    const float* gf    = (const float*)d_in[13];
    const float* bf    = (const float*)d_in[14];

    float *xg, *xng, *qkvg, *dotsg, *wTg;
    __nv_bfloat16 *attnbg, *vTbg, *qbg, *kbg;
    uint32_t* maskg;
    cudaGetSymbolAddress((void**)&xg,     g_x);
    cudaGetSymbolAddress((void**)&xng,    g_xn);
    cudaGetSymbolAddress((void**)&qkvg,   g_qkv);
    cudaGetSymbolAddress((void**)&dotsg,  g_dots);
    cudaGetSymbolAddress((void**)&attnbg, g_attnb);
    cudaGetSymbolAddress((void**)&vTbg,   g_vTb);
    cudaGetSymbolAddress((void**)&qbg,    g_qb);
    cudaGetSymbolAddress((void**)&kbg,    g_kb);
    cudaGetSymbolAddress((void**)&wTg,    g_wT);
    cudaGetSymbolAddress((void**)&maskg,  g_mask);

    cudaFuncSetAttribute(gemm_tc_k, cudaFuncAttributeMaxDynamicSharedMemorySize, GEMM_TC_SMEM);
    cudaFuncSetAttribute(gemm_bf_k, cudaFuncAttributeMaxDynamicSharedMemorySize, GEMM_BF_SMEM);

    float* out_x    = (float*)d_out;
    float* out_attn = out_x + (size_t)ROWS * DIM64;
    float* out_ds   = out_attn + (size_t)NTOK * NTOK;

    dim3 blk(16, 16);
    dim3 tblk(32, 8);
    const size_t avHalf = (size_t)NTOK * 512;   // split-K partial stride (in g_dots)

    for (int l = 0; l < 2; l++) {
        const float* src = l ? xg : embed;
        // xn = LN(x)
        ln_k<<<ROWS / 8, 256>>>(src, g1 + l * 64, b1 + l * 64, xng, ROWS);
        // wT = Wqkv[l]^T
        transpose_k<<<dim3(768 / 32, 64 / 32, 1), tblk>>>(
            Wqkv + (size_t)l * 64 * 768, 768, 0, wTg, 64, 0);
        // qkv = xn @ Wqkv[l] (NT): [8192,64] x [768,64]^T
        gemm_tc_k<<<dim3(768 / 128, ROWS / 128, 1), 128, GEMM_TC_SMEM>>>(
            xng, 64, 0, wTg, 64, 0, qkvg, 768, 0, 64, 1.0f);
        // peel q*0.125, k (batch 0) to bf16
        qk_to_bf_k<<<NTOK * 64 / 256, 256>>>(qkvg, qbg, kbg);
        // dots = (0.125 q0) @ k0^T in bf16
        gemm_bf_k<<<dim3(NTOK / 128, NTOK / 128, 1), 128, GEMM_BF_SMEM>>>(
            qbg, 256, 0, kbg, 256, 0, dotsg, NTOK, 0, 256);
        // softmax -> bf16 attn (+ fp32/ds outputs on last layer)
        if (l == 0)
            attn_softmax_k<<<NTOK, 256>>>(dotsg, Am, attnbg, maskg);
        else
            dual_softmax_k<<<NTOK, 256>>>(dotsg, maskg, out_attn, attnbg, out_ds);
        // vT bf16 (both batches -> [512][4096])
        transpose_bf_k<<<dim3(INNERD / 32, NTOK / 32, BATCH), tblk>>>(
            qkvg + 512, 768, (size_t)NTOK * 768,
            vTbg, NTOK, (size_t)INNERD * NTOK);
        // av = attn @ vT^T in bf16, split-K x2 (fp32 partials into free dots scratch)
        gemm_bf_k<<<dim3(512 / 128, NTOK / 128, 2), 128, GEMM_BF_SMEM>>>(
            attnbg, NTOK, 2048, vTbg, NTOK, 2048, dotsg, 512, avHalf, 2048);
        // x[z] = xn[z] + ((p0+p1)[:, z*256..] @ Wout[l] + bout[l]) — split-K add fused
        gemm_k<<<dim3(1, NTOK / 64, 2), blk>>>(
            dotsg, dotsg + avHalf, 512, (size_t)INNERD,
            Wout + (size_t)l * INNERD * 64, 64,
            xg, 64, (size_t)NTOK * 64, INNERD,
            bout + l * 64, xng, 64, (size_t)NTOK * 64, 0);
        // xm = LN(x)
        ln_k<<<ROWS / 8, 256>>>(xg, g2 + l * 64, b2 + l * 64, xng, ROWS);
        // h = gelu(xm @ W1 + bb1)
        gemm_k<<<dim3(1, ROWS / 64, 1), blk>>>(
            xng, nullptr, 64, 0, W1 + (size_t)l * 64 * 64, 64, qkvg, 64, 0, 64,
            bb1 + l * 64, nullptr, 64, 0, 1);
        // x = xm + (h @ W2 + bb2)
        gemm_k<<<dim3(1, ROWS / 64, 1), blk>>>(
            qkvg, nullptr, 64, 0, W2 + (size_t)l * 64 * 64, 64, xg, 64, 0, 64,
            bb2 + l * 64, xng, 64, 0, 0);
    }
    // final LN -> output
    ln_k<<<ROWS / 8, 256>>>(xg, gf, bf, out_x, ROWS);
}

// round 17
// speedup vs baseline: 2.0930x; 1.0219x over previous
#include <cuda_runtime.h>
#include <cuda_bf16.h>
#include <math.h>
#include <stdint.h>

#define NTOK   4096
#define BATCH  2
#define DIM64  64
#define INNERD 256
#define ROWS   (BATCH * NTOK)   // 8192

// -------------------- device scratch --------------------
__device__ float g_xn  [ROWS * DIM64];                  // xn / xm (in-place through the layer)
__device__ float g_qkv [ROWS * INNERD * 3];
__device__ float g_dots[(size_t)NTOK * NTOK];           // reused as split-K partials after softmax
__device__ __nv_bfloat16 g_attnb[(size_t)NTOK * NTOK];  // bf16 attn for the AV GEMM
__device__ __nv_bfloat16 g_vTb [BATCH * INNERD * NTOK]; // bf16 [512][4096]
__device__ __nv_bfloat16 g_qb  [NTOK * INNERD];         // bf16 q (x0.125), batch 0
__device__ __nv_bfloat16 g_kb  [NTOK * INNERD];         // bf16 k, batch 0
__device__ float g_wT  [2 * 768 * 64];                  // both layers' Wqkv^T
__device__ uint32_t g_mask[NTOK * 128];                 // adjacency bitmask, built in layer 0

// -------------------- helpers --------------------
__device__ __forceinline__ void mma_tf32(float c[4], const float a[4], const float b[2]) {
    asm volatile(
        "mma.sync.aligned.m16n8k8.row.col.f32.tf32.tf32.f32 "
        "{%0,%1,%2,%3}, {%4,%5,%6,%7}, {%8,%9}, {%0,%1,%2,%3};"
        : "+f"(c[0]), "+f"(c[1]), "+f"(c[2]), "+f"(c[3])
        : "r"(__float_as_uint(a[0])), "r"(__float_as_uint(a[1])),
          "r"(__float_as_uint(a[2])), "r"(__float_as_uint(a[3])),
          "r"(__float_as_uint(b[0])), "r"(__float_as_uint(b[1])));
}

__device__ __forceinline__ void mma_bf16(float c[4], const uint32_t a[4],
                                         uint32_t b0, uint32_t b1) {
    asm volatile(
        "mma.sync.aligned.m16n8k16.row.col.f32.bf16.bf16.f32 "
        "{%0,%1,%2,%3}, {%4,%5,%6,%7}, {%8,%9}, {%0,%1,%2,%3};"
        : "+f"(c[0]), "+f"(c[1]), "+f"(c[2]), "+f"(c[3])
        : "r"(a[0]), "r"(a[1]), "r"(a[2]), "r"(a[3]), "r"(b0), "r"(b1));
}

__device__ __forceinline__ void cp16(uint32_t dst, const void* src) {
    asm volatile("cp.async.cg.shared.global [%0], [%1], 16;" :: "r"(dst), "l"(src));
}

__device__ __forceinline__ uint32_t pack_bf2(float a, float b) {
    __nv_bfloat162 h = __floats2bfloat162_rn(a, b);
    return *(uint32_t*)&h;
}

// ==================== TF32 tensor-core NT GEMM (qkv projection only) ============
#define SPITCH 36
#define ASTG   (128 * SPITCH)
#define AS(p, m, k) sm[(p) * ASTG + (m) * SPITCH + (k)]
#define BS(p, n, k) sm[(2 + (p)) * ASTG + (n) * SPITCH + (k)]
#define GEMM_TC_SMEM (4 * ASTG * (int)sizeof(float))   // 73728 bytes

__global__ void __launch_bounds__(128, 2)
gemm_tc_k(const float* __restrict__ A, int lda, size_t sAz,
          const float* __restrict__ B, int ldb, size_t sBz,
          float* __restrict__ C, int ldc, size_t sCz,
          int K, float alpha)
{
    extern __shared__ float sm[];
    const uint32_t smb = (uint32_t)__cvta_generic_to_shared(sm);
    const int tid  = threadIdx.x;
    const int wid  = tid >> 5, lane = tid & 31;
    const int wm   = wid & 1,  wn   = wid >> 1;
    const int gid  = lane >> 2, tig = lane & 3;
    const int m0   = blockIdx.y * 128, n0 = blockIdx.x * 128;

    A += (size_t)blockIdx.z * sAz;
    B += (size_t)blockIdx.z * sBz;
    C += (size_t)blockIdx.z * sCz;

    int lrow[8], lkq[8];
    #pragma unroll
    for (int i = 0; i < 8; i++) {
        int c = tid + i * 128;
        lrow[i] = c >> 3;
        lkq[i]  = (c & 7) << 2;
    }

#define ISSUE(s, kt)                                                                     \
    {                                                                                    \
        const int _k0 = (kt) << 5;                                                       \
        _Pragma("unroll")                                                                \
        for (int i = 0; i < 8; i++) {                                                    \
            cp16(smb + (uint32_t)((((s) * ASTG) + lrow[i] * SPITCH + lkq[i]) * 4),       \
                 A + (size_t)(m0 + lrow[i]) * lda + _k0 + lkq[i]);                       \
            cp16(smb + (uint32_t)((((2 + (s)) * ASTG) + lrow[i] * SPITCH + lkq[i]) * 4), \
                 B + (size_t)(n0 + lrow[i]) * ldb + _k0 + lkq[i]);                       \
        }                                                                                \
        asm volatile("cp.async.commit_group;");                                         \
    }

    float acc[4][8][4];
    #pragma unroll
    for (int mt = 0; mt < 4; mt++)
        #pragma unroll
        for (int nt = 0; nt < 8; nt++)
            #pragma unroll
            for (int q = 0; q < 4; q++) acc[mt][nt][q] = 0.0f;

    const int KT = K >> 5;
    ISSUE(0, 0);

    for (int kt = 0; kt < KT; kt++) {
        const int p = kt & 1;
        if (kt + 1 < KT) {
            ISSUE(p ^ 1, kt + 1);
            asm volatile("cp.async.wait_group 1;");
        } else {
            asm volatile("cp.async.wait_group 0;");
        }
        __syncthreads();

        #pragma unroll
        for (int ks = 0; ks < 4; ks++) {
            const int kb = ks << 3;
            float fa[4][4];
            float fb[8][2];
            #pragma unroll
            for (int mt = 0; mt < 4; mt++) {
                const int mr = wm * 64 + mt * 16 + gid;
                fa[mt][0] = AS(p, mr,     kb + tig);
                fa[mt][1] = AS(p, mr + 8, kb + tig);
                fa[mt][2] = AS(p, mr,     kb + tig + 4);
                fa[mt][3] = AS(p, mr + 8, kb + tig + 4);
            }
            #pragma unroll
            for (int nt = 0; nt < 8; nt++) {
                const int nr = wn * 64 + nt * 8 + gid;
                fb[nt][0] = BS(p, nr, kb + tig);
                fb[nt][1] = BS(p, nr, kb + tig + 4);
            }
            #pragma unroll
            for (int nt = 0; nt < 8; nt++)
                #pragma unroll
                for (int mt = 0; mt < 4; mt++)
                    mma_tf32(acc[mt][nt], fa[mt], fb[nt]);
        }
        __syncthreads();
    }

    #pragma unroll
    for (int mt = 0; mt < 4; mt++) {
        const int row = m0 + wm * 64 + mt * 16 + gid;
        #pragma unroll
        for (int nt = 0; nt < 8; nt++) {
            const int col = n0 + wn * 64 + nt * 8 + tig * 2;
            float2 v0 = make_float2(acc[mt][nt][0] * alpha, acc[mt][nt][1] * alpha);
            float2 v1 = make_float2(acc[mt][nt][2] * alpha, acc[mt][nt][3] * alpha);
            *(float2*)(C + (size_t)row * ldc + col)       = v0;
            *(float2*)(C + (size_t)(row + 8) * ldc + col) = v1;
        }
    }
#undef ISSUE
}

// ==================== BF16 tensor-core NT GEMM (QK^T and attn @ V) ============
#define BPITCH 36
#define BSTG   (128 * BPITCH)
#define GEMM_BF_SMEM (4 * BSTG * 4)     // 73728 bytes

__global__ void __launch_bounds__(128, 2)
gemm_bf_k(const __nv_bfloat16* __restrict__ A, int lda, size_t sAz,
          const __nv_bfloat16* __restrict__ B, int ldb, size_t sBz,
          float* __restrict__ C, int ldc, size_t sCz,
          int K)
{
    extern __shared__ uint32_t smu[];
    const uint32_t smb = (uint32_t)__cvta_generic_to_shared(smu);
    const int tid  = threadIdx.x;
    const int wid  = tid >> 5, lane = tid & 31;
    const int wm   = wid & 1,  wn   = wid >> 1;
    const int gid  = lane >> 2, tig = lane & 3;
    const int m0   = blockIdx.y * 128, n0 = blockIdx.x * 128;

    A += (size_t)blockIdx.z * sAz;
    B += (size_t)blockIdx.z * sBz;
    C += (size_t)blockIdx.z * sCz;

    int lrow[8], lcc[8];
    #pragma unroll
    for (int i = 0; i < 8; i++) {
        int c = tid + i * 128;
        lrow[i] = c >> 3;
        lcc[i]  = c & 7;
    }

#define BISSUE(s, kt)                                                                      \
    {                                                                                      \
        const int _k0 = (kt) << 6;                                                         \
        _Pragma("unroll")                                                                  \
        for (int i = 0; i < 8; i++) {                                                      \
            cp16(smb + (uint32_t)((((s) * BSTG) + lrow[i] * BPITCH) * 4 + lcc[i] * 16),    \
                 A + (size_t)(m0 + lrow[i]) * lda + _k0 + lcc[i] * 8);                     \
            cp16(smb + (uint32_t)((((2 + (s)) * BSTG) + lrow[i] * BPITCH) * 4 + lcc[i] * 16), \
                 B + (size_t)(n0 + lrow[i]) * ldb + _k0 + lcc[i] * 8);                     \
        }                                                                                  \
        asm volatile("cp.async.commit_group;");                                           \
    }

    float acc[4][8][4];
    #pragma unroll
    for (int mt = 0; mt < 4; mt++)
        #pragma unroll
        for (int nt = 0; nt < 8; nt++)
            #pragma unroll
            for (int q = 0; q < 4; q++) acc[mt][nt][q] = 0.0f;

    const int KT = K >> 6;
    BISSUE(0, 0);

    for (int kt = 0; kt < KT; kt++) {
        const int p = kt & 1;
        if (kt + 1 < KT) {
            BISSUE(p ^ 1, kt + 1);
            asm volatile("cp.async.wait_group 1;");
        } else {
            asm volatile("cp.async.wait_group 0;");
        }
        __syncthreads();

        #pragma unroll
        for (int ks = 0; ks < 4; ks++) {
            uint32_t fa[4][4], fb[8][2];
            #pragma unroll
            for (int mt = 0; mt < 4; mt++) {
                const int mr = wm * 64 + mt * 16 + gid;
                const int base = p * BSTG + mr * BPITCH + ks * 8 + tig;
                fa[mt][0] = smu[base];
                fa[mt][1] = smu[base + 8 * BPITCH];
                fa[mt][2] = smu[base + 4];
                fa[mt][3] = smu[base + 8 * BPITCH + 4];
            }
            #pragma unroll
            for (int nt = 0; nt < 8; nt++) {
                const int nr = wn * 64 + nt * 8 + gid;
                const int bb = (2 + p) * BSTG + nr * BPITCH + ks * 8 + tig;
                fb[nt][0] = smu[bb];
                fb[nt][1] = smu[bb + 4];
            }
            #pragma unroll
            for (int nt = 0; nt < 8; nt++)
                #pragma unroll
                for (int mt = 0; mt < 4; mt++)
                    mma_bf16(acc[mt][nt], fa[mt], fb[nt][0], fb[nt][1]);
        }
        __syncthreads();
    }

    #pragma unroll
    for (int mt = 0; mt < 4; mt++) {
        const int row = m0 + wm * 64 + mt * 16 + gid;
        #pragma unroll
        for (int nt = 0; nt < 8; nt++) {
            const int col = n0 + wn * 64 + nt * 8 + tig * 2;
            *(float2*)(C + (size_t)row * ldc + col)       = make_float2(acc[mt][nt][0], acc[mt][nt][1]);
            *(float2*)(C + (size_t)(row + 8) * ldc + col) = make_float2(acc[mt][nt][2], acc[mt][nt][3]);
        }
    }
#undef BISSUE
}

// ---- peel q (x0.125) and k from fp32 qkv into contiguous bf16 [4096,256] ----
__global__ void qk_to_bf_k(const float* __restrict__ qkv,
                           __nv_bfloat16* __restrict__ qb, __nv_bfloat16* __restrict__ kb)
{
    int i = blockIdx.x * 256 + threadIdx.x;
    int row = i >> 6, c4 = (i & 63) << 2;
    const float4 q4 = *(const float4*)(qkv + (size_t)row * 768 + c4);
    const float4 k4 = *(const float4*)(qkv + (size_t)row * 768 + 256 + c4);
    uint2 uq, uk;
    uq.x = pack_bf2(q4.x * 0.125f, q4.y * 0.125f);
    uq.y = pack_bf2(q4.z * 0.125f, q4.w * 0.125f);
    uk.x = pack_bf2(k4.x, k4.y);
    uk.y = pack_bf2(k4.z, k4.w);
    *(uint2*)(qb + (size_t)row * 256 + c4) = uq;
    *(uint2*)(kb + (size_t)row * 256 + c4) = uk;
}

// -------------------- transposes --------------------
__global__ void transpose_k(const float* __restrict__ src, int lds, size_t sSz,
                            float* __restrict__ dst, int ldd, size_t sDz)
{
    __shared__ float t[32][33];
    src += (size_t)blockIdx.z * sSz;
    dst += (size_t)blockIdx.z * sDz;
    int c0 = blockIdx.x * 32, r0 = blockIdx.y * 32;
    int tx = threadIdx.x, ty = threadIdx.y;
    #pragma unroll
    for (int j = 0; j < 32; j += 8)
        t[ty + j][tx] = src[(size_t)(r0 + ty + j) * lds + c0 + tx];
    __syncthreads();
    #pragma unroll
    for (int j = 0; j < 32; j += 8)
        dst[(size_t)(c0 + ty + j) * ldd + r0 + tx] = t[tx][ty + j];
}

__global__ void transpose_bf_k(const float* __restrict__ src, int lds, size_t sSz,
                               __nv_bfloat16* __restrict__ dst, int ldd, size_t sDz)
{
    __shared__ float t[32][33];
    src += (size_t)blockIdx.z * sSz;
    dst += (size_t)blockIdx.z * sDz;
    int c0 = blockIdx.x * 32, r0 = blockIdx.y * 32;
    int tx = threadIdx.x, ty = threadIdx.y;
    #pragma unroll
    for (int j = 0; j < 32; j += 8)
        t[ty + j][tx] = src[(size_t)(r0 + ty + j) * lds + c0 + tx];
    __syncthreads();
    #pragma unroll
    for (int j = 0; j < 32; j += 8)
        dst[(size_t)(c0 + ty + j) * ldd + r0 + tx] = __float2bfloat16_rn(t[tx][ty + j]);
}

// -------------------- standalone LayerNorm (only for the initial embed) --------------------
__global__ void ln_k(const float* __restrict__ x, const float* __restrict__ g,
                     const float* __restrict__ b, float* __restrict__ y, int rows)
{
    int w    = blockIdx.x * 8 + (threadIdx.x >> 5);
    int lane = threadIdx.x & 31;
    if (w >= rows) return;
    const float* xr = x + (size_t)w * 64;
    float v0 = xr[lane], v1 = xr[lane + 32];
    float s = v0 + v1;
    #pragma unroll
    for (int o = 16; o > 0; o >>= 1) s += __shfl_xor_sync(0xffffffffu, s, o);
    float m  = s * (1.0f / 64.0f);
    float d0 = v0 - m, d1 = v1 - m;
    float q  = d0 * d0 + d1 * d1;
    #pragma unroll
    for (int o = 16; o > 0; o >>= 1) q += __shfl_xor_sync(0xffffffffu, q, o);
    float inv = rsqrtf(q * (1.0f / 64.0f) + 1e-5f);
    float* yr = y + (size_t)w * 64;
    yr[lane]      = d0 * inv * g[lane]      + b[lane];
    yr[lane + 32] = d1 * inv * g[lane + 32] + b[lane + 32];
}

// ---- small fp32 GEMM, N=64, grid.x==1. Optional split-K add (A2), gelu, residual, and
// ---- fused LayerNorm over the 64-wide row (lng/lnb non-null => write LN(v) instead of v).
__global__ void __launch_bounds__(256)
gemm_k(const float* __restrict__ A, const float* __restrict__ A2, int lda, size_t sAz,
       const float* __restrict__ B, int ldb,
       float* __restrict__ C, int ldc, size_t sCz,
       int K,
       const float* __restrict__ bias,
       const float* __restrict__ resid, int ldr, size_t sRz,
       int do_gelu,
       const float* __restrict__ lng, const float* __restrict__ lnb)
{
    __shared__ float As[16][68];
    __shared__ float Bs[16][68];
    int tx = threadIdx.x, ty = threadIdx.y;
    int t  = ty * 16 + tx;
    int m0 = blockIdx.y * 64, n0 = blockIdx.x * 64;

    A += (size_t)blockIdx.z * sAz;
    if (A2) A2 += (size_t)blockIdx.z * sAz;
    C += (size_t)blockIdx.z * sCz;
    if (resid) resid += (size_t)blockIdx.z * sRz;

    float acc[4][4] = {};
    int ar  = t / 4;
    int ac4 = (t % 4) * 4;
    int br  = t / 16;
    int bc4 = (t % 16) * 4;

    for (int k0 = 0; k0 < K; k0 += 16) {
        const size_t aoff = (size_t)(m0 + ar) * lda + k0 + ac4;
        if (A2) {
            #pragma unroll
            for (int q = 0; q < 4; q++) As[ac4 + q][ar] = A[aoff + q] + A2[aoff + q];
        } else {
            #pragma unroll
            for (int q = 0; q < 4; q++) As[ac4 + q][ar] = A[aoff + q];
        }
        const float* Bp = B + (size_t)(k0 + br) * ldb + n0 + bc4;
        #pragma unroll
        for (int q = 0; q < 4; q++) Bs[br][bc4 + q] = Bp[q];
        __syncthreads();
        #pragma unroll
        for (int kk = 0; kk < 16; kk++) {
            float a[4], b[4];
            #pragma unroll
            for (int i = 0; i < 4; i++) a[i] = As[kk][ty * 4 + i];
            #pragma unroll
            for (int j = 0; j < 4; j++) b[j] = Bs[kk][tx * 4 + j];
            #pragma unroll
            for (int i = 0; i < 4; i++)
                #pragma unroll
                for (int j = 0; j < 4; j++)
                    acc[i][j] = fmaf(a[i], b[j], acc[i][j]);
        }
        __syncthreads();
    }

    // finalize values (bias / gelu / residual)
    #pragma unroll
    for (int i = 0; i < 4; i++) {
        int row = m0 + ty * 4 + i;
        #pragma unroll
        for (int j = 0; j < 4; j++) {
            int col = n0 + tx * 4 + j;
            float v = acc[i][j];
            if (bias)    v += bias[col];
            if (do_gelu) v = 0.5f * v * (1.0f + erff(v * 0.70710678118654752f));
            if (resid)   v += resid[(size_t)row * ldr + col];
            acc[i][j] = v;
        }
    }

    if (lng) {
        // fused LayerNorm: the 64 cols of each row live across the 16 tx lanes
        #pragma unroll
        for (int i = 0; i < 4; i++) {
            float s = (acc[i][0] + acc[i][1]) + (acc[i][2] + acc[i][3]);
            float q = (acc[i][0] * acc[i][0] + acc[i][1] * acc[i][1])
                    + (acc[i][2] * acc[i][2] + acc[i][3] * acc[i][3]);
            #pragma unroll
            for (int o = 8; o > 0; o >>= 1) {
                s += __shfl_xor_sync(0xffffffffu, s, o);
                q += __shfl_xor_sync(0xffffffffu, q, o);
            }
            float m   = s * (1.0f / 64.0f);
            float var = q * (1.0f / 64.0f) - m * m;
            float inv = rsqrtf(var + 1e-5f);
            int row = m0 + ty * 4 + i;
            #pragma unroll
            for (int j = 0; j < 4; j++) {
                int col = n0 + tx * 4 + j;
                C[(size_t)row * ldc + col] = (acc[i][j] - m) * inv * lng[col] + lnb[col];
            }
        }
    } else {
        #pragma unroll
        for (int i = 0; i < 4; i++) {
            int row = m0 + ty * 4 + i;
            #pragma unroll
            for (int j = 0; j < 4; j++)
                C[(size_t)row * ldc + n0 + tx * 4 + j] = acc[i][j];
        }
    }
}

// -------------------- block reductions --------------------
__device__ __forceinline__ float blk_max(float v, float* wred, int wid, int lane) {
    #pragma unroll
    for (int o = 16; o > 0; o >>= 1) v = fmaxf(v, __shfl_xor_sync(0xffffffffu, v, o));
    if (lane == 0) wred[wid] = v;
    __syncthreads();
    float r = wred[0];
    #pragma unroll
    for (int i = 1; i < 8; i++) r = fmaxf(r, wred[i]);
    __syncthreads();
    return r;
}
__device__ __forceinline__ float blk_sum(float v, float* wred, int wid, int lane) {
    #pragma unroll
    for (int o = 16; o > 0; o >>= 1) v += __shfl_xor_sync(0xffffffffu, v, o);
    if (lane == 0) wred[wid] = v;
    __syncthreads();
    float r = 0.0f;
    #pragma unroll
    for (int i = 0; i < 8; i++) r += wred[i];
    __syncthreads();
    return r;
}

// ---- layer-0 masked softmax: reads fp32 A, writes bf16 attn AND the bitmask ----
__global__ void attn_softmax_k(const float* __restrict__ dots, const float* __restrict__ Am,
                               __nv_bfloat16* __restrict__ attnb, uint32_t* __restrict__ maskw)
{
    __shared__ float wred[8];
    __shared__ uint32_t mw[128];
    const int row = blockIdx.x, tid = threadIdx.x;
    const int wid = tid >> 5, lane = tid & 31;
    const float4* dr = (const float4*)(dots + (size_t)row * NTOK);
    const float4* ar = (const float4*)(Am   + (size_t)row * NTOK);
    const int dj = row >> 2, dl = row & 3;

    if (tid < 128) mw[tid] = 0u;
    __syncthreads();

    float4 r[4];
    float mx = -3.4e38f;
    #pragma unroll
    for (int i = 0; i < 4; i++) {
        int j = tid + i * 256;
        float4 d = dr[j], a = ar[j], v;
        uint32_t bits = 0;
        v.x = (a.x > 0.0f) ? (bits |= 1u, d.x) : -9e15f;
        v.y = (a.y > 0.0f) ? (bits |= 2u, d.y) : -9e15f;
        v.z = (a.z > 0.0f) ? (bits |= 4u, d.z) : -9e15f;
        v.w = (a.w > 0.0f) ? (bits |= 8u, d.w) : -9e15f;
        if (bits) atomicOr(&mw[j >> 3], bits << ((j & 7) * 4));
        if (j == dj) ((float*)&v)[dl] = 1.0f;
        r[i] = v;
        mx = fmaxf(fmaxf(fmaxf(mx, v.x), v.y), fmaxf(v.z, v.w));
    }
    mx = blk_max(mx, wred, wid, lane);

    float sum = 0.0f;
    #pragma unroll
    for (int i = 0; i < 4; i++) {
        r[i].x = __expf(r[i].x - mx); r[i].y = __expf(r[i].y - mx);
        r[i].z = __expf(r[i].z - mx); r[i].w = __expf(r[i].w - mx);
        sum += (r[i].x + r[i].y) + (r[i].z + r[i].w);
    }
    sum = blk_sum(sum, wred, wid, lane);
    float inv = 1.0f / sum;

    uint2* ob = (uint2*)(attnb + (size_t)row * NTOK);
    #pragma unroll
    for (int i = 0; i < 4; i++) {
        int j = tid + i * 256;
        uint2 u;
        u.x = pack_bf2(r[i].x * inv, r[i].y * inv);
        u.y = pack_bf2(r[i].z * inv, r[i].w * inv);
        ob[j] = u;
    }
    __syncthreads();
    if (tid < 128) maskw[row * 128 + tid] = mw[tid];
}

// ---- layer-1: masked softmax -> fp32 attn_out + bf16 attnb; plain softmax -> ds_out ----
// exp-sharing: exp(d-mxm) = exp(d-mxr) * exp(mxr-mxm) for unmasked elements.
__global__ void dual_softmax_k(const float* __restrict__ dots, const uint32_t* __restrict__ maskw,
                               float* __restrict__ attn_out, __nv_bfloat16* __restrict__ attnb,
                               float* __restrict__ ds_out)
{
    __shared__ float wred[8];
    const int row = blockIdx.x, tid = threadIdx.x;
    const int wid = tid >> 5, lane = tid & 31;
    const float4* dr = (const float4*)(dots + (size_t)row * NTOK);
    const uint32_t* mrow = maskw + row * 128;
    const int dj = row >> 2, dl = row & 3;

    float4 rv[4], mv[4];
    uint32_t bt[4];
    float mxr = -3.4e38f, mxm = -3.4e38f;
    #pragma unroll
    for (int i = 0; i < 4; i++) {
        int j = tid + i * 256;
        float4 d = dr[j];
        uint32_t bits = (mrow[j >> 3] >> ((j & 7) * 4)) & 0xFu;
        bt[i] = bits;
        rv[i] = d;
        mxr = fmaxf(fmaxf(fmaxf(mxr, d.x), d.y), fmaxf(d.z, d.w));
        float vm = -3.4e38f;
        if (bits & 1u) vm = fmaxf(vm, d.x);
        if (bits & 2u) vm = fmaxf(vm, d.y);
        if (bits & 4u) vm = fmaxf(vm, d.z);
        if (bits & 8u) vm = fmaxf(vm, d.w);
        if (j == dj) vm = fmaxf(vm, 1.0f);
        mxm = fmaxf(mxm, vm);
    }
    mxm = blk_max(mxm, wred, wid, lane);
    mxr = blk_max(mxr, wred, wid, lane);
    const float sc   = __expf(mxr - mxm);
    const float diag = __expf(1.0f - mxm);

    float sm = 0.0f, sr = 0.0f;
    #pragma unroll
    for (int i = 0; i < 4; i++) {
        int j = tid + i * 256;
        float4 er;
        er.x = __expf(rv[i].x - mxr); er.y = __expf(rv[i].y - mxr);
        er.z = __expf(rv[i].z - mxr); er.w = __expf(rv[i].w - mxr);
        rv[i] = er;
        sr += (er.x + er.y) + (er.z + er.w);
        float4 em;
        em.x = (bt[i] & 1u) ? er.x * sc : 0.0f;
        em.y = (bt[i] & 2u) ? er.y * sc : 0.0f;
        em.z = (bt[i] & 4u) ? er.z * sc : 0.0f;
        em.w = (bt[i] & 8u) ? er.w * sc : 0.0f;
        if (j == dj) ((float*)&em)[dl] = diag;
        mv[i] = em;
        sm += (em.x + em.y) + (em.z + em.w);
    }
    sm = blk_sum(sm, wred, wid, lane);
    sr = blk_sum(sr, wred, wid, lane);
    float invm = 1.0f / sm, invr = 1.0f / sr;

    float4* o2 = (float4*)(attn_out + (size_t)row * NTOK);
    uint2*  ob = (uint2*)(attnb + (size_t)row * NTOK);
    float4* o3 = (float4*)(ds_out   + (size_t)row * NTOK);
    #pragma unroll
    for (int i = 0; i < 4; i++) {
        int j = tid + i * 256;
        float4 vo = make_float4(mv[i].x * invm, mv[i].y * invm, mv[i].z * invm, mv[i].w * invm);
        o2[j] = vo;
        uint2 u;
        u.x = pack_bf2(vo.x, vo.y);
        u.y = pack_bf2(vo.z, vo.w);
        ob[j] = u;
        o3[j] = make_float4(rv[i].x * invr, rv[i].y * invr, rv[i].z * invr, rv[i].w * invr);
    }
}

// -------------------- host orchestration --------------------
extern "C" void kernel_launch(void* const* d_in, const int* in_sizes, int n_in,
                              void* d_out, int out_size)
{
    const float* embed = (const float*)d_in[0];
    const float* Am    = (const float*)d_in[1];
    const float* g1    = (const float*)d_in[2];
    const float* b1    = (const float*)d_in[3];
    const float* Wqkv  = (const float*)d_in[4];
    const float* Wout  = (const float*)d_in[5];
    const float* bout  = (const float*)d_in[6];
    const float* g2    = (const float*)d_in[7];
    const float* b2    = (const float*)d_in[8];
    const float* W1    = (const float*)d_in[9];
    const float* bb1   = (const float*)d_in[10];
    const float* W2    = (const float*)d_in[11];
    const float* bb2   = (const float*)d_in[12];
    const float* gf    = (const float*)d_in[13];
    const float* bf    = (const float*)d_in[14];

    float *xng, *qkvg, *dotsg, *wTg;
    __nv_bfloat16 *attnbg, *vTbg, *qbg, *kbg;
    uint32_t* maskg;
    cudaGetSymbolAddress((void**)&xng,    g_xn);
    cudaGetSymbolAddress((void**)&qkvg,   g_qkv);
    cudaGetSymbolAddress((void**)&dotsg,  g_dots);
    cudaGetSymbolAddress((void**)&attnbg, g_attnb);
    cudaGetSymbolAddress((void**)&vTbg,   g_vTb);
    cudaGetSymbolAddress((void**)&qbg,    g_qb);
    cudaGetSymbolAddress((void**)&kbg,    g_kb);
    cudaGetSymbolAddress((void**)&wTg,    g_wT);
    cudaGetSymbolAddress((void**)&maskg,  g_mask);

    cudaFuncSetAttribute(gemm_tc_k, cudaFuncAttributeMaxDynamicSharedMemorySize, GEMM_TC_SMEM);
    cudaFuncSetAttribute(gemm_bf_k, cudaFuncAttributeMaxDynamicSharedMemorySize, GEMM_BF_SMEM);

    float* out_x    = (float*)d_out;
    float* out_attn = out_x + (size_t)ROWS * DIM64;
    float* out_ds   = out_attn + (size_t)NTOK * NTOK;

    dim3 blk(16, 16);
    dim3 tblk(32, 8);
    const size_t avHalf = (size_t)NTOK * 512;   // split-K partial stride (in g_dots)

    // initial LN (embed -> xn) and both layers' Wqkv^T (hoisted)
    ln_k<<<ROWS / 8, 256>>>(embed, g1, b1, xng, ROWS);
    transpose_k<<<dim3(768 / 32, 64 / 32, 2), tblk>>>(
        Wqkv, 768, (size_t)64 * 768, wTg, 64, (size_t)768 * 64);

    for (int l = 0; l < 2; l++) {
        // qkv = xn @ Wqkv[l] (NT): [8192,64] x [768,64]^T
        gemm_tc_k<<<dim3(768 / 128, ROWS / 128, 1), 128, GEMM_TC_SMEM>>>(
            xng, 64, 0, wTg + (size_t)l * 768 * 64, 64, 0, qkvg, 768, 0, 64, 1.0f);
        // peel q*0.125, k (batch 0) to bf16
        qk_to_bf_k<<<NTOK * 64 / 256, 256>>>(qkvg, qbg, kbg);
        // dots = (0.125 q0) @ k0^T in bf16
        gemm_bf_k<<<dim3(NTOK / 128, NTOK / 128, 1), 128, GEMM_BF_SMEM>>>(
            qbg, 256, 0, kbg, 256, 0, dotsg, NTOK, 0, 256);
        // softmax -> bf16 attn (+ fp32/ds outputs on last layer)
        if (l == 0)
            attn_softmax_k<<<NTOK, 256>>>(dotsg, Am, attnbg, maskg);
        else
            dual_softmax_k<<<NTOK, 256>>>(dotsg, maskg, out_attn, attnbg, out_ds);
        // vT bf16 (both batches -> [512][4096])
        transpose_bf_k<<<dim3(INNERD / 32, NTOK / 32, BATCH), tblk>>>(
            qkvg + 512, 768, (size_t)NTOK * 768,
            vTbg, NTOK, (size_t)INNERD * NTOK);
        // av = attn @ vT^T in bf16, split-K x2 (fp32 partials into free dots scratch)
        gemm_bf_k<<<dim3(512 / 128, NTOK / 128, 2), 128, GEMM_BF_SMEM>>>(
            attnbg, NTOK, 2048, vTbg, NTOK, 2048, dotsg, 512, avHalf, 2048);
        // xm = LN2( xn + (p0+p1) @ Wout + bout )  — split-K add AND LN fused; writes xng
        gemm_k<<<dim3(1, NTOK / 64, 2), blk>>>(
            dotsg, dotsg + avHalf, 512, (size_t)INNERD,
            Wout + (size_t)l * INNERD * 64, 64,
            xng, 64, (size_t)NTOK * 64, INNERD,
            bout + l * 64, xng, 64, (size_t)NTOK * 64, 0,
            g2 + l * 64, b2 + l * 64);
        // h = gelu(xm @ W1 + bb1)
        gemm_k<<<dim3(1, ROWS / 64, 1), blk>>>(
            xng, nullptr, 64, 0, W1 + (size_t)l * 64 * 64, 64, qkvg, 64, 0, 64,
            bb1 + l * 64, nullptr, 64, 0, 1, nullptr, nullptr);
        // x = xm + (h @ W2 + bb2), fused with next LN:
        //   layer 0: ln1(layer1) -> xng ;  layer 1: final LN -> out_x
        const float* lg = (l == 0) ? (g1 + 64) : gf;
        const float* lb = (l == 0) ? (b1 + 64) : bf;
        float* dst = (l == 0) ? xng : out_x;
        gemm_k<<<dim3(1, ROWS / 64, 1), blk>>>(
            qkvg, nullptr, 64, 0, W2 + (size_t)l * 64 * 64, 64, dst, 64, 0, 64,
            bb2 + l * 64, xng, 64, 0, 0, lg, lb);
    }
}